// round 9
// baseline (speedup 1.0000x reference)
#include <cuda_runtime.h>
#include <stdint.h>

#define NB    8
#define NCH   3
#define HH    160
#define NH    40
#define NPIX  1600     // 40*40
#define KEIG  10
#define MLAN  320      // Lanczos depth
#define NBLK  128      // persistent blocks (<= SM count for co-residency)
#define NTHR  256
#define NWARP (NBLK*NTHR/32)   // 1024 global warps
#define NSTR  16               // reorth stripes
#define ISTR  (MLAN/NSTR)      // 20 vectors per stripe

// ---------------- device scratch (static globals; no allocation) ----------------
static __device__ float  g_t1[NB*NCH*HH*NH];      // width-downsampled
static __device__ float  g_ds[NB*NCH*NPIX];       // fully downsampled
static __device__ float  g_F[NPIX*3];             // normalized 3-vectors (batch 0)
static __device__ float  g_A[NPIX*NPIX];          // D^-1/2 W D^-1/2
static __device__ double g_deg[NPIX];
static __device__ float  g_dinv[NPIX];
static __device__ float  g_V[(size_t)MLAN*NPIX];  // Lanczos basis
static __device__ float  g_w0[NPIX], g_w1[NPIX], g_w2[NPIX];
static __device__ float  g_up[NSTR*NPIX];         // striped reorth partials
static __device__ float  g_c1[MLAN];              // reorth coeffs (pass 1)
static __device__ float  g_c2[MLAN];              // reorth coeffs (pass 2)
static __device__ float  g_alphaA[MLAN];
static __device__ float  g_betaA[MLAN+1];
static __device__ float  g_nrm[NBLK];             // per-block norm^2 partials
static __device__ unsigned g_bar;                 // software grid barrier counter
static __device__ float  g_lan12[2*NB*KEIG];
static __device__ float  g_lan3[KEIG];

__constant__ float c_bw[8] = {1.f,3.f,5.f,7.f,7.f,5.f,3.f,1.f};

// ---------------- downsample: jax.image.resize(bilinear, antialias=True), 4x ----
__global__ void k_ds_h(const float* __restrict__ feats){
    int idx = blockIdx.x*blockDim.x + threadIdx.x;
    if (idx >= NB*NCH*HH*NH) return;
    int ox = idx % NH;
    int y  = (idx / NH) % HH;
    int bc = idx / (NH*HH);
    const float* row = feats + ((size_t)bc*HH + y)*HH;
    int j0 = 4*ox - 2;
    float acc = 0.f, ws = 0.f;
    #pragma unroll
    for (int t = 0; t < 8; t++){
        int j = j0 + t;
        if (j >= 0 && j < HH){ acc += c_bw[t]*row[j]; ws += c_bw[t]; }
    }
    g_t1[idx] = acc/ws;
}

__global__ void k_ds_v(){
    int idx = blockIdx.x*blockDim.x + threadIdx.x;
    if (idx >= NB*NCH*NH*NH) return;
    int ox = idx % NH;
    int oy = (idx / NH) % NH;
    int bc = idx / (NH*NH);
    int j0 = 4*oy - 2;
    float acc = 0.f, ws = 0.f;
    #pragma unroll
    for (int t = 0; t < 8; t++){
        int j = j0 + t;
        if (j >= 0 && j < HH){ acc += c_bw[t]*g_t1[((size_t)bc*HH + j)*NH + ox]; ws += c_bw[t]; }
    }
    g_ds[idx] = acc/ws;
}

// -------- lan1/lan2 (C=1): spectrum exactly {0 per nonempty sign class, 1 rest} --
__global__ void k_signs(){
    __shared__ int sp[256], sn[256];
    int blk = blockIdx.x;           // 0..15
    int b = blk >> 1, ch = blk & 1;
    int tid = threadIdx.x;
    const float* base = g_ds + (size_t)(b*NCH + ch)*NPIX;
    int cp = 0, cn = 0;
    for (int p = tid; p < NPIX; p += 256){
        float x = base[p];
        cp += (x > 0.f); cn += (x < 0.f);
    }
    sp[tid] = cp; sn[tid] = cn; __syncthreads();
    for (int s = 128; s > 0; s >>= 1){
        if (tid < s){ sp[tid] += sp[tid+s]; sn[tid] += sn[tid+s]; }
        __syncthreads();
    }
    if (tid == 0){
        int ncomp = (sp[0] > 0) + (sn[0] > 0);
        float* lan = g_lan12 + ch*NB*KEIG + b*KEIG;
        for (int k = 0; k < KEIG; k++) lan[k] = (k < ncomp) ? 0.f : 1.f;
    }
}

// -------- lan3 path: batch 0, all 3 channels ------------------------------------
__global__ void k_buildF(){
    int p = blockIdx.x*blockDim.x + threadIdx.x;
    if (p >= NPIX) return;
    float x0 = g_ds[p], x1 = g_ds[NPIX + p], x2 = g_ds[2*NPIX + p];
    float nrm = sqrtf(x0*x0 + x1*x1 + x2*x2);
    float den = fmaxf(nrm, 1e-12f);
    g_F[p*3+0] = x0/den; g_F[p*3+1] = x1/den; g_F[p*3+2] = x2/den;
}

__global__ void k_buildA(){
    __shared__ float sF[NPIX*3];
    __shared__ double red[256];
    int tid = threadIdx.x;
    for (int t = tid; t < NPIX*3; t += 256) sF[t] = g_F[t];
    __syncthreads();
    int i = blockIdx.x;
    float f0 = sF[3*i], f1 = sF[3*i+1], f2 = sF[3*i+2];
    float* rowp = g_A + (size_t)i*NPIX;
    double acc = 0.0;
    for (int j = tid; j < NPIX; j += 256){
        float s = f0*sF[3*j] + f1*sF[3*j+1] + f2*sF[3*j+2];
        s = (s > 0.f) ? s : 0.f;
        rowp[j] = s;
        acc += (double)s;
    }
    red[tid] = acc; __syncthreads();
    for (int s = 128; s > 0; s >>= 1){ if (tid < s) red[tid] += red[tid+s]; __syncthreads(); }
    if (tid == 0) g_deg[i] = red[0];   // W.max() scaling cancels in D^-1/2 W D^-1/2
}

__global__ void k_dinv(){
    int p = blockIdx.x*blockDim.x + threadIdx.x;
    if (p >= NPIX) return;
    g_dinv[p] = (float)(1.0/sqrt(g_deg[p]));   // deg >= 1 (diag is 1)
}

__global__ void k_scaleA(){
    int idx = blockIdx.x*blockDim.x + threadIdx.x;
    if (idx >= NPIX*NPIX) return;
    int i = idx / NPIX, j = idx % NPIX;
    g_A[idx] *= g_dinv[i]*g_dinv[j];
}

// -------- persistent Lanczos (CGS2: double-pass full reorthogonalization) ---------
__global__ void k_reset(){ g_bar = 0u; }

__device__ __forceinline__ void gridbar(unsigned* step){
    __syncthreads();
    if (threadIdx.x == 0){
        unsigned tgt = (++(*step)) * (unsigned)NBLK;
        __threadfence();
        atomicAdd(&g_bar, 1u);
        while (*((volatile unsigned*)&g_bar) < tgt) __nanosleep(64);
        __threadfence();   // gpu-scope fence -> CCTL.IVALL invalidates this SM's L1
    }
    __syncthreads();
}

// deterministic per-block sum of squares -> g_nrm[bid]
__device__ __forceinline__ void blocknorm(float x, float* swred){
    int lane = threadIdx.x & 31, wip = threadIdx.x >> 5;
    float s = x;
    #pragma unroll
    for (int o = 16; o; o >>= 1) s += __shfl_down_sync(0xffffffffu, s, o);
    if (lane == 0) swred[wip] = s;
    __syncthreads();
    if (threadIdx.x == 0){
        float t = 0.f;
        #pragma unroll
        for (int i = 0; i < NTHR/32; i++) t += swred[i];
        g_nrm[blockIdx.x] = t;
    }
}

// warp-per-vector dots: c[i] = V[i] . g_w2  (caller stages g_w2 in smem)
__device__ __forceinline__ void dotphase(int j, float* sw, float* cdst,
                                         int bid, int tid, int lane, int gw){
    if (bid*(NTHR/32) <= j){
        for (int t = tid; t < NPIX; t += NTHR) sw[t] = g_w2[t];
        __syncthreads();
        int i = gw;
        if (i <= j){
            const float* vi = g_V + (size_t)i*NPIX;
            float acc = 0.f;
            for (int t = lane; t < NPIX; t += 32) acc += vi[t]*sw[t];
            #pragma unroll
            for (int o = 16; o; o >>= 1) acc += __shfl_down_sync(0xffffffffu, acc, o);
            if (lane == 0) cdst[i] = acc;
        }
    }
}

// striped partials: g_up[s][t] = sum_{i in stripe s, i<=j} c[i]*V[i][t]
__device__ __forceinline__ void stripephase(int j, const float* c, int gt){
    int s = gt / NPIX;
    if (s < NSTR){
        int t  = gt - s*NPIX;
        int lo = s*ISTR;
        int hi = lo + ISTR; if (hi > j+1) hi = j+1;
        float acc = 0.f;
        for (int i = lo; i < hi; i++) acc += c[i]*g_V[(size_t)i*NPIX + t];
        g_up[s*NPIX + t] = acc;
    }
}

__global__ void __launch_bounds__(NTHR) k_lanczos(){
    __shared__ float sw[NPIX];
    __shared__ float swred[NTHR/32];
    __shared__ float sbinv;
    int tid = threadIdx.x, bid = blockIdx.x;
    int lane = tid & 31, wip = tid >> 5;
    int gw = bid*(NTHR/32) + wip;      // global warp 0..1023
    int gt = bid*NTHR + tid;           // global thread 0..32767
    unsigned bstep = 0;

    // ---- init random w0 + its per-block norm partials ----
    float x = 0.f;
    if (gt < NPIX){
        unsigned u = (unsigned)gt*2654435761u + 1234567u;
        u ^= u >> 13; u *= 2246822519u; u ^= u >> 16;
        float v = ((float)(u & 0x7FFFFF))/4194304.0f - 1.0f;
        g_w0[gt] = v;
        x = v*v;
    }
    blocknorm(x, swred);
    gridbar(&bstep);

    for (int j = 0; j < MLAN; j++){
        const float* wI = (j & 1) ? g_w1 : g_w0;
        float*       wN = (j & 1) ? g_w0 : g_w1;

        // ---- M: beta_j, v_j = w/beta, w2 = (I - A) v_j ----
        if (tid == 0){
            double s = 0.0;
            #pragma unroll 8
            for (int i = 0; i < NBLK; i++) s += (double)g_nrm[i];
            float beta = (float)sqrt(s);
            if (beta < 1e-30f) beta = 1e-30f;
            sbinv = 1.0f/beta;
            if (bid == 0) g_betaA[j] = beta;
        }
        for (int t = tid; t < NPIX; t += NTHR) sw[t] = wI[t];
        __syncthreads();
        float binv = sbinv;
        if (gt < NPIX) g_V[(size_t)j*NPIX + gt] = sw[gt]*binv;
        for (int r = gw; r < NPIX; r += NWARP){
            const float* row = g_A + (size_t)r*NPIX;
            float acc = 0.f;
            for (int t = lane; t < NPIX; t += 32) acc += row[t]*sw[t];
            #pragma unroll
            for (int o = 16; o; o >>= 1) acc += __shfl_down_sync(0xffffffffu, acc, o);
            if (lane == 0) g_w2[r] = (sw[r] - acc)*binv;
        }
        gridbar(&bstep);

        // ---- reorth pass 1: dots ----
        dotphase(j, sw, g_c1, bid, tid, lane, gw);
        gridbar(&bstep);
        // ---- pass-1 striped partials ----
        stripephase(j, g_c1, gt);
        gridbar(&bstep);
        // ---- apply pass 1: u1 = w2 - sum_s parts (in place) ----
        if (gt < NPIX){
            float v = g_w2[gt];
            #pragma unroll
            for (int s = 0; s < NSTR; s++) v -= g_up[s*NPIX + gt];
            g_w2[gt] = v;
        }
        gridbar(&bstep);

        // ---- reorth pass 2: dots on u1 ----
        dotphase(j, sw, g_c2, bid, tid, lane, gw);
        gridbar(&bstep);
        // ---- pass-2 striped partials ----
        stripephase(j, g_c2, gt);
        gridbar(&bstep);
        // ---- apply pass 2: w_next = u1 - sum_s parts; norm; alpha_j ----
        float xx = 0.f;
        if (gt < NPIX){
            float v = g_w2[gt];
            #pragma unroll
            for (int s = 0; s < NSTR; s++) v -= g_up[s*NPIX + gt];
            wN[gt] = v;
            xx = v*v;
        }
        blocknorm(xx, swred);
        if (gt == 0) g_alphaA[j] = g_c1[j] + g_c2[j];
        gridbar(&bstep);
    }
}

// -------- tridiagonal bottom-K via Sturm multisection -----------------------------
__device__ __forceinline__ int sturm_count(float lam, const float* a, const float* b){
    float d = a[0] - lam;
    if (d == 0.f) d = -1e-25f;
    int c = (d < 0.f);
    for (int i = 1; i < MLAN; i++){
        d = (a[i] - lam) - (b[i]*b[i])/d;
        if (d == 0.f) d = -1e-25f;
        c += (d < 0.f);
    }
    return c;
}

__global__ void k_trieig(){
    __shared__ float sa[MLAN], sb[MLAN];
    __shared__ int   scnt[1024];
    __shared__ float sblo[KEIG], sbhi[KEIG];
    __shared__ float slo, shi;
    int tid = threadIdx.x;
    for (int i = tid; i < MLAN; i += 1024){
        sa[i] = g_alphaA[i];
        sb[i] = (i == 0) ? 0.f : g_betaA[i];  // sb[i] couples (i-1,i)
    }
    __syncthreads();
    if (tid == 0){
        float lo = 1e30f, hi = -1e30f;
        for (int i = 0; i < MLAN; i++){
            float r = fabsf(sb[i]) + ((i+1 < MLAN) ? fabsf(sb[i+1]) : 0.f);
            lo = fminf(lo, sa[i] - r);
            hi = fmaxf(hi, sa[i] + r);
        }
        slo = lo - 1e-4f; shi = hi + 1e-4f;
    }
    __syncthreads();
    {
        float lam = slo + (shi - slo)*((float)tid/1023.f);
        scnt[tid] = sturm_count(lam, sa, sb);
    }
    __syncthreads();
    if (tid < KEIG){
        int k = tid, tl = 0;
        for (int t = 1; t < 1024; t++) if (scnt[t] <= k) tl = t;
        sblo[k] = slo + (shi - slo)*((float)tl/1023.f);
        sbhi[k] = slo + (shi - slo)*((float)(tl+1)/1023.f);
    }
    __syncthreads();
    for (int round = 0; round < 3; round++){
        int k = tid/100, g = tid%100;
        if (tid < 1000){
            float lam = sblo[k] + (sbhi[k] - sblo[k])*((float)(g+1)/101.f);
            scnt[tid] = sturm_count(lam, sa, sb);
        }
        __syncthreads();
        if (tid < KEIG){
            int k2 = tid, gl = -1;
            for (int g2 = 0; g2 < 100; g2++) if (scnt[k2*100 + g2] <= k2) gl = g2;
            float lo = sblo[k2], w = sbhi[k2] - lo;
            sblo[k2] = lo + w*((float)(gl+1)/101.f);
            sbhi[k2] = lo + w*((float)(gl+2)/101.f);
        }
        __syncthreads();
    }
    if (tid < KEIG) g_lan3[tid] = 0.5f*(sblo[tid] + sbhi[tid]);
}

// -------- final loss ---------------------------------------------------------------
__global__ void k_loss(float* __restrict__ out){
    if (blockIdx.x == 0 && threadIdx.x == 0){
        double s12 = 0.0, s13 = 0.0, s23 = 0.0;
        for (int b = 0; b < NB; b++){
            for (int k = 0; k < KEIG; k++){
                double l1 = (double)g_lan12[b*KEIG + k];
                double l2 = (double)g_lan12[NB*KEIG + b*KEIG + k];
                double l3 = (double)g_lan3[k];
                double d;
                d = l1 - l2; s12 += d*d;
                d = l1 - l3; s13 += d*d;
                d = l2 - l3; s23 += d*d;
            }
        }
        out[0] = (float)(5.0*((s12 + s13 + s23)/(double)(NB*KEIG)));
    }
}

// -------- launch (11 graph nodes total) ---------------------------------------------
extern "C" void kernel_launch(void* const* d_in, const int* in_sizes, int n_in,
                              void* d_out, int out_size){
    const float* feats = (const float*)d_in[0];
    (void)in_sizes; (void)n_in; (void)out_size;   // K = 10, shapes fixed

    k_ds_h<<<(NB*NCH*HH*NH + 255)/256, 256>>>(feats);
    k_ds_v<<<(NB*NCH*NH*NH + 255)/256, 256>>>();
    k_signs<<<2*NB, 256>>>();

    k_buildF<<<(NPIX + 255)/256, 256>>>();
    k_buildA<<<NPIX, 256>>>();
    k_dinv<<<(NPIX + 255)/256, 256>>>();
    k_scaleA<<<(NPIX*NPIX + 255)/256, 256>>>();

    k_reset<<<1, 1>>>();
    k_lanczos<<<NBLK, NTHR>>>();
    k_trieig<<<1, 1024>>>();
    k_loss<<<1, 32>>>((float*)d_out);
}

// round 10
// speedup vs baseline: 1.0107x; 1.0107x over previous
#include <cuda_runtime.h>
#include <stdint.h>

#define NB    8
#define NCH   3
#define HH    160
#define NH    40
#define NPIX  1600     // 40*40
#define KEIG  10
#define MLAN  320      // Lanczos depth
#define NBLK  128      // persistent blocks (<= SM count for co-residency)
#define NTHR  256
#define NWARP (NBLK*NTHR/32)   // 1024 global warps
#define NSTR  16               // reorth stripes
#define ISTR  (MLAN/NSTR)      // 20 vectors per stripe

// ---------------- device scratch (static globals; no allocation) ----------------
static __device__ float  g_t1[NB*NCH*HH*NH];      // width-downsampled
static __device__ float  g_ds[NB*NCH*NPIX];       // fully downsampled
static __device__ float  g_F[NPIX*3];             // normalized 3-vectors (batch 0)
static __device__ float  g_A[NPIX*NPIX];          // D^-1/2 W D^-1/2
static __device__ double g_deg[NPIX];
static __device__ float  g_dinv[NPIX];
static __device__ float  g_V[(size_t)MLAN*NPIX];  // Lanczos basis
static __device__ float  g_w0[NPIX], g_w1[NPIX], g_w2[NPIX];
static __device__ float  g_up[NSTR*NPIX];         // striped reorth partials
static __device__ float  g_c1[MLAN];              // reorth coeffs (pass 1)
static __device__ float  g_c2[MLAN];              // reorth coeffs (pass 2)
static __device__ float  g_alphaA[MLAN];
static __device__ float  g_betaA[MLAN+1];
static __device__ float  g_nrm[NBLK];             // per-block norm^2 partials
static __device__ unsigned g_bar;                 // software grid barrier counter
static __device__ float  g_lan12[2*NB*KEIG];
static __device__ float  g_lan3[KEIG];

__constant__ float c_bw[8] = {1.f,3.f,5.f,7.f,7.f,5.f,3.f,1.f};

// ---------------- downsample: jax.image.resize(bilinear, antialias=True), 4x ----
__global__ void k_ds_h(const float* __restrict__ feats){
    int idx = blockIdx.x*blockDim.x + threadIdx.x;
    if (idx >= NB*NCH*HH*NH) return;
    int ox = idx % NH;
    int y  = (idx / NH) % HH;
    int bc = idx / (NH*HH);
    const float* row = feats + ((size_t)bc*HH + y)*HH;
    int j0 = 4*ox - 2;
    float acc = 0.f, ws = 0.f;
    #pragma unroll
    for (int t = 0; t < 8; t++){
        int j = j0 + t;
        if (j >= 0 && j < HH){ acc += c_bw[t]*row[j]; ws += c_bw[t]; }
    }
    g_t1[idx] = acc/ws;
}

__global__ void k_ds_v(){
    int idx = blockIdx.x*blockDim.x + threadIdx.x;
    if (idx >= NB*NCH*NH*NH) return;
    int ox = idx % NH;
    int oy = (idx / NH) % NH;
    int bc = idx / (NH*NH);
    int j0 = 4*oy - 2;
    float acc = 0.f, ws = 0.f;
    #pragma unroll
    for (int t = 0; t < 8; t++){
        int j = j0 + t;
        if (j >= 0 && j < HH){ acc += c_bw[t]*g_t1[((size_t)bc*HH + j)*NH + ox]; ws += c_bw[t]; }
    }
    g_ds[idx] = acc/ws;
}

// -------- lan1/lan2 (C=1): spectrum exactly {0 per nonempty sign class, 1 rest} --
__global__ void k_signs(){
    __shared__ int sp[256], sn[256];
    int blk = blockIdx.x;           // 0..15
    int b = blk >> 1, ch = blk & 1;
    int tid = threadIdx.x;
    const float* base = g_ds + (size_t)(b*NCH + ch)*NPIX;
    int cp = 0, cn = 0;
    for (int p = tid; p < NPIX; p += 256){
        float x = base[p];
        cp += (x > 0.f); cn += (x < 0.f);
    }
    sp[tid] = cp; sn[tid] = cn; __syncthreads();
    for (int s = 128; s > 0; s >>= 1){
        if (tid < s){ sp[tid] += sp[tid+s]; sn[tid] += sn[tid+s]; }
        __syncthreads();
    }
    if (tid == 0){
        int ncomp = (sp[0] > 0) + (sn[0] > 0);
        float* lan = g_lan12 + ch*NB*KEIG + b*KEIG;
        for (int k = 0; k < KEIG; k++) lan[k] = (k < ncomp) ? 0.f : 1.f;
    }
}

// -------- lan3 path: batch 0, all 3 channels ------------------------------------
__global__ void k_buildF(){
    int p = blockIdx.x*blockDim.x + threadIdx.x;
    if (p >= NPIX) return;
    float x0 = g_ds[p], x1 = g_ds[NPIX + p], x2 = g_ds[2*NPIX + p];
    float nrm = sqrtf(x0*x0 + x1*x1 + x2*x2);
    float den = fmaxf(nrm, 1e-12f);
    g_F[p*3+0] = x0/den; g_F[p*3+1] = x1/den; g_F[p*3+2] = x2/den;
}

__global__ void k_buildA(){
    __shared__ float sF[NPIX*3];
    __shared__ double red[256];
    int tid = threadIdx.x;
    for (int t = tid; t < NPIX*3; t += 256) sF[t] = g_F[t];
    __syncthreads();
    int i = blockIdx.x;
    float f0 = sF[3*i], f1 = sF[3*i+1], f2 = sF[3*i+2];
    float* rowp = g_A + (size_t)i*NPIX;
    double acc = 0.0;
    for (int j = tid; j < NPIX; j += 256){
        float s = f0*sF[3*j] + f1*sF[3*j+1] + f2*sF[3*j+2];
        s = (s > 0.f) ? s : 0.f;
        rowp[j] = s;
        acc += (double)s;
    }
    red[tid] = acc; __syncthreads();
    for (int s = 128; s > 0; s >>= 1){ if (tid < s) red[tid] += red[tid+s]; __syncthreads(); }
    if (tid == 0) g_deg[i] = red[0];   // W.max() scaling cancels in D^-1/2 W D^-1/2
}

__global__ void k_dinv(){
    int p = blockIdx.x*blockDim.x + threadIdx.x;
    if (p >= NPIX) return;
    g_dinv[p] = (float)(1.0/sqrt(g_deg[p]));   // deg >= 1 (diag is 1)
}

__global__ void k_scaleA(){
    int idx = blockIdx.x*blockDim.x + threadIdx.x;
    if (idx >= NPIX*NPIX) return;
    int i = idx / NPIX, j = idx % NPIX;
    g_A[idx] *= g_dinv[i]*g_dinv[j];
}

// -------- persistent Lanczos (CGS2: double-pass full reorthogonalization) ---------
__global__ void k_reset(){ g_bar = 0u; }

__device__ __forceinline__ void gridbar(unsigned* step){
    __syncthreads();
    if (threadIdx.x == 0){
        unsigned tgt = (++(*step)) * (unsigned)NBLK;
        __threadfence();
        atomicAdd(&g_bar, 1u);
        while (*((volatile unsigned*)&g_bar) < tgt) __nanosleep(64);
        __threadfence();   // gpu-scope fence -> CCTL.IVALL invalidates this SM's L1
    }
    __syncthreads();
}

// deterministic per-block sum of squares -> g_nrm[bid]
__device__ __forceinline__ void blocknorm(float x, float* swred){
    int lane = threadIdx.x & 31, wip = threadIdx.x >> 5;
    float s = x;
    #pragma unroll
    for (int o = 16; o; o >>= 1) s += __shfl_down_sync(0xffffffffu, s, o);
    if (lane == 0) swred[wip] = s;
    __syncthreads();
    if (threadIdx.x == 0){
        float t = 0.f;
        #pragma unroll
        for (int i = 0; i < NTHR/32; i++) t += swred[i];
        g_nrm[blockIdx.x] = t;
    }
}

// warp-per-vector dots: c[i] = V[i] . g_w2  (caller stages g_w2 in smem)
__device__ __forceinline__ void dotphase(int j, float* sw, float* cdst,
                                         int bid, int tid, int lane, int gw){
    if (bid*(NTHR/32) <= j){
        for (int t = tid; t < NPIX; t += NTHR) sw[t] = g_w2[t];
        __syncthreads();
        int i = gw;
        if (i <= j){
            const float* vi = g_V + (size_t)i*NPIX;
            float acc = 0.f;
            for (int t = lane; t < NPIX; t += 32) acc += vi[t]*sw[t];
            #pragma unroll
            for (int o = 16; o; o >>= 1) acc += __shfl_down_sync(0xffffffffu, acc, o);
            if (lane == 0) cdst[i] = acc;
        }
    }
}

// striped partials: g_up[s][t] = sum_{i in stripe s, i<=j} c[i]*V[i][t]
__device__ __forceinline__ void stripephase(int j, const float* c, int gt){
    int s = gt / NPIX;
    if (s < NSTR){
        int t  = gt - s*NPIX;
        int lo = s*ISTR;
        int hi = lo + ISTR; if (hi > j+1) hi = j+1;
        float acc = 0.f;
        for (int i = lo; i < hi; i++) acc += c[i]*g_V[(size_t)i*NPIX + t];
        g_up[s*NPIX + t] = acc;
    }
}

__global__ void __launch_bounds__(NTHR) k_lanczos(){
    __shared__ float sw[NPIX];
    __shared__ float swred[NTHR/32];
    __shared__ float sbinv;
    int tid = threadIdx.x, bid = blockIdx.x;
    int lane = tid & 31, wip = tid >> 5;
    int gw = bid*(NTHR/32) + wip;      // global warp 0..1023
    int gt = bid*NTHR + tid;           // global thread 0..32767
    unsigned bstep = 0;

    // ---- init random w0 + its per-block norm partials ----
    float x = 0.f;
    if (gt < NPIX){
        unsigned u = (unsigned)gt*2654435761u + 1234567u;
        u ^= u >> 13; u *= 2246822519u; u ^= u >> 16;
        float v = ((float)(u & 0x7FFFFF))/4194304.0f - 1.0f;
        g_w0[gt] = v;
        x = v*v;
    }
    blocknorm(x, swred);
    gridbar(&bstep);

    for (int j = 0; j < MLAN; j++){
        const float* wI = (j & 1) ? g_w1 : g_w0;
        float*       wN = (j & 1) ? g_w0 : g_w1;

        // ---- M: beta_j, v_j = w/beta, w2 = (I - A) v_j ----
        if (tid == 0){
            double s = 0.0;
            #pragma unroll 8
            for (int i = 0; i < NBLK; i++) s += (double)g_nrm[i];
            float beta = (float)sqrt(s);
            if (beta < 1e-30f) beta = 1e-30f;
            sbinv = 1.0f/beta;
            if (bid == 0) g_betaA[j] = beta;
        }
        for (int t = tid; t < NPIX; t += NTHR) sw[t] = wI[t];
        __syncthreads();
        float binv = sbinv;
        if (gt < NPIX) g_V[(size_t)j*NPIX + gt] = sw[gt]*binv;
        for (int r = gw; r < NPIX; r += NWARP){
            const float* row = g_A + (size_t)r*NPIX;
            float acc = 0.f;
            for (int t = lane; t < NPIX; t += 32) acc += row[t]*sw[t];
            #pragma unroll
            for (int o = 16; o; o >>= 1) acc += __shfl_down_sync(0xffffffffu, acc, o);
            if (lane == 0) g_w2[r] = (sw[r] - acc)*binv;
        }
        gridbar(&bstep);

        // ---- reorth pass 1: dots ----
        dotphase(j, sw, g_c1, bid, tid, lane, gw);
        gridbar(&bstep);
        // ---- pass-1 striped partials ----
        stripephase(j, g_c1, gt);
        gridbar(&bstep);
        // ---- apply pass 1: u1 = w2 - sum_s parts (in place) ----
        if (gt < NPIX){
            float v = g_w2[gt];
            #pragma unroll
            for (int s = 0; s < NSTR; s++) v -= g_up[s*NPIX + gt];
            g_w2[gt] = v;
        }
        gridbar(&bstep);

        // ---- reorth pass 2: dots on u1 ----
        dotphase(j, sw, g_c2, bid, tid, lane, gw);
        gridbar(&bstep);
        // ---- pass-2 striped partials ----
        stripephase(j, g_c2, gt);
        gridbar(&bstep);
        // ---- apply pass 2: w_next = u1 - sum_s parts; norm; alpha_j ----
        float xx = 0.f;
        if (gt < NPIX){
            float v = g_w2[gt];
            #pragma unroll
            for (int s = 0; s < NSTR; s++) v -= g_up[s*NPIX + gt];
            wN[gt] = v;
            xx = v*v;
        }
        blocknorm(xx, swred);
        if (gt == 0) g_alphaA[j] = g_c1[j] + g_c2[j];
        gridbar(&bstep);
    }
}

// -------- tridiagonal bottom-K via Sturm multisection -----------------------------
__device__ __forceinline__ int sturm_count(float lam, const float* a, const float* b){
    float d = a[0] - lam;
    if (d == 0.f) d = -1e-25f;
    int c = (d < 0.f);
    for (int i = 1; i < MLAN; i++){
        d = (a[i] - lam) - (b[i]*b[i])/d;
        if (d == 0.f) d = -1e-25f;
        c += (d < 0.f);
    }
    return c;
}

__global__ void k_trieig(){
    __shared__ float sa[MLAN], sb[MLAN];
    __shared__ int   scnt[1024];
    __shared__ float sblo[KEIG], sbhi[KEIG];
    __shared__ float slo, shi;
    int tid = threadIdx.x;
    for (int i = tid; i < MLAN; i += 1024){
        sa[i] = g_alphaA[i];
        sb[i] = (i == 0) ? 0.f : g_betaA[i];  // sb[i] couples (i-1,i)
    }
    __syncthreads();
    if (tid == 0){
        float lo = 1e30f, hi = -1e30f;
        for (int i = 0; i < MLAN; i++){
            float r = fabsf(sb[i]) + ((i+1 < MLAN) ? fabsf(sb[i+1]) : 0.f);
            lo = fminf(lo, sa[i] - r);
            hi = fmaxf(hi, sa[i] + r);
        }
        slo = lo - 1e-4f; shi = hi + 1e-4f;
    }
    __syncthreads();
    {
        float lam = slo + (shi - slo)*((float)tid/1023.f);
        scnt[tid] = sturm_count(lam, sa, sb);
    }
    __syncthreads();
    if (tid < KEIG){
        int k = tid, tl = 0;
        for (int t = 1; t < 1024; t++) if (scnt[t] <= k) tl = t;
        sblo[k] = slo + (shi - slo)*((float)tl/1023.f);
        sbhi[k] = slo + (shi - slo)*((float)(tl+1)/1023.f);
    }
    __syncthreads();
    for (int round = 0; round < 3; round++){
        int k = tid/100, g = tid%100;
        if (tid < 1000){
            float lam = sblo[k] + (sbhi[k] - sblo[k])*((float)(g+1)/101.f);
            scnt[tid] = sturm_count(lam, sa, sb);
        }
        __syncthreads();
        if (tid < KEIG){
            int k2 = tid, gl = -1;
            for (int g2 = 0; g2 < 100; g2++) if (scnt[k2*100 + g2] <= k2) gl = g2;
            float lo = sblo[k2], w = sbhi[k2] - lo;
            sblo[k2] = lo + w*((float)(gl+1)/101.f);
            sbhi[k2] = lo + w*((float)(gl+2)/101.f);
        }
        __syncthreads();
    }
    if (tid < KEIG) g_lan3[tid] = 0.5f*(sblo[tid] + sbhi[tid]);
}

// -------- final loss ---------------------------------------------------------------
__global__ void k_loss(float* __restrict__ out){
    if (blockIdx.x == 0 && threadIdx.x == 0){
        double s12 = 0.0, s13 = 0.0, s23 = 0.0;
        for (int b = 0; b < NB; b++){
            for (int k = 0; k < KEIG; k++){
                double l1 = (double)g_lan12[b*KEIG + k];
                double l2 = (double)g_lan12[NB*KEIG + b*KEIG + k];
                double l3 = (double)g_lan3[k];
                double d;
                d = l1 - l2; s12 += d*d;
                d = l1 - l3; s13 += d*d;
                d = l2 - l3; s23 += d*d;
            }
        }
        out[0] = (float)(5.0*((s12 + s13 + s23)/(double)(NB*KEIG)));
    }
}

// -------- launch (11 graph nodes total) ---------------------------------------------
extern "C" void kernel_launch(void* const* d_in, const int* in_sizes, int n_in,
                              void* d_out, int out_size){
    const float* feats = (const float*)d_in[0];
    (void)in_sizes; (void)n_in; (void)out_size;   // K = 10, shapes fixed

    k_ds_h<<<(NB*NCH*HH*NH + 255)/256, 256>>>(feats);
    k_ds_v<<<(NB*NCH*NH*NH + 255)/256, 256>>>();
    k_signs<<<2*NB, 256>>>();

    k_buildF<<<(NPIX + 255)/256, 256>>>();
    k_buildA<<<NPIX, 256>>>();
    k_dinv<<<(NPIX + 255)/256, 256>>>();
    k_scaleA<<<(NPIX*NPIX + 255)/256, 256>>>();

    k_reset<<<1, 1>>>();
    k_lanczos<<<NBLK, NTHR>>>();
    k_trieig<<<1, 1024>>>();
    k_loss<<<1, 32>>>((float*)d_out);
}

// round 11
// speedup vs baseline: 1.3823x; 1.3676x over previous
#include <cuda_runtime.h>
#include <stdint.h>

#define NB    8
#define NCH   3
#define HH    160
#define NH    40
#define NPIX  1600     // 40*40
#define KEIG  10
#define MLAN  256      // Lanczos depth
#define NBLK  128      // persistent blocks (<= SM count for co-residency)
#define NTHR  256
#define NWARP (NBLK*NTHR/32)   // 1024 global warps
#define NSTR  16               // reorth stripes (per output column)
#define ISTR  (MLAN/NSTR)      // 16 vectors per stripe
#define TPB_T 16               // output columns per block in stripe/apply phase
#define SBLK  (NPIX/TPB_T)     // 100 blocks active in stripe/apply

// ---------------- device scratch (static globals; no allocation) ----------------
static __device__ float  g_t1[NB*NCH*HH*NH];      // width-downsampled
static __device__ float  g_ds[NB*NCH*NPIX];       // fully downsampled
static __device__ float  g_F[NPIX*3];             // normalized 3-vectors (batch 0)
static __device__ float  g_A[NPIX*NPIX];          // D^-1/2 W D^-1/2
static __device__ double g_deg[NPIX];
static __device__ float  g_dinv[NPIX];
static __device__ float  g_V[(size_t)MLAN*NPIX];  // Lanczos basis
static __device__ float  g_w0[NPIX], g_w1[NPIX];  // residual ping-pong
static __device__ float  g_w2[NPIX];              // (I-A)v_j
static __device__ float  g_u1[NPIX];              // after reorth pass 1
static __device__ float  g_c1[MLAN];              // reorth coeffs (pass 1)
static __device__ float  g_c2[MLAN];              // reorth coeffs (pass 2)
static __device__ float  g_alphaA[MLAN];
static __device__ float  g_betaA[MLAN+1];
static __device__ float  g_nrm[NBLK];             // per-block norm^2 partials
static __device__ unsigned g_bar;                 // software grid barrier counter
static __device__ float  g_lan12[2*NB*KEIG];
static __device__ float  g_lan3[KEIG];

__constant__ float c_bw[8] = {1.f,3.f,5.f,7.f,7.f,5.f,3.f,1.f};

// ---------------- downsample: jax.image.resize(bilinear, antialias=True), 4x ----
__global__ void k_ds_h(const float* __restrict__ feats){
    int idx = blockIdx.x*blockDim.x + threadIdx.x;
    if (idx >= NB*NCH*HH*NH) return;
    int ox = idx % NH;
    int y  = (idx / NH) % HH;
    int bc = idx / (NH*HH);
    const float* row = feats + ((size_t)bc*HH + y)*HH;
    int j0 = 4*ox - 2;
    float acc = 0.f, ws = 0.f;
    #pragma unroll
    for (int t = 0; t < 8; t++){
        int j = j0 + t;
        if (j >= 0 && j < HH){ acc += c_bw[t]*row[j]; ws += c_bw[t]; }
    }
    g_t1[idx] = acc/ws;
}

__global__ void k_ds_v(){
    int idx = blockIdx.x*blockDim.x + threadIdx.x;
    if (idx >= NB*NCH*NH*NH) return;
    int ox = idx % NH;
    int oy = (idx / NH) % NH;
    int bc = idx / (NH*NH);
    int j0 = 4*oy - 2;
    float acc = 0.f, ws = 0.f;
    #pragma unroll
    for (int t = 0; t < 8; t++){
        int j = j0 + t;
        if (j >= 0 && j < HH){ acc += c_bw[t]*g_t1[((size_t)bc*HH + j)*NH + ox]; ws += c_bw[t]; }
    }
    g_ds[idx] = acc/ws;
}

// -------- lan1/lan2 (C=1): spectrum exactly {0 per nonempty sign class, 1 rest} --
__global__ void k_signs(){
    __shared__ int sp[256], sn[256];
    int blk = blockIdx.x;           // 0..15
    int b = blk >> 1, ch = blk & 1;
    int tid = threadIdx.x;
    const float* base = g_ds + (size_t)(b*NCH + ch)*NPIX;
    int cp = 0, cn = 0;
    for (int p = tid; p < NPIX; p += 256){
        float x = base[p];
        cp += (x > 0.f); cn += (x < 0.f);
    }
    sp[tid] = cp; sn[tid] = cn; __syncthreads();
    for (int s = 128; s > 0; s >>= 1){
        if (tid < s){ sp[tid] += sp[tid+s]; sn[tid] += sn[tid+s]; }
        __syncthreads();
    }
    if (tid == 0){
        int ncomp = (sp[0] > 0) + (sn[0] > 0);
        float* lan = g_lan12 + ch*NB*KEIG + b*KEIG;
        for (int k = 0; k < KEIG; k++) lan[k] = (k < ncomp) ? 0.f : 1.f;
    }
}

// -------- lan3 path: batch 0, all 3 channels ------------------------------------
__global__ void k_buildF(){
    int p = blockIdx.x*blockDim.x + threadIdx.x;
    if (p >= NPIX) return;
    float x0 = g_ds[p], x1 = g_ds[NPIX + p], x2 = g_ds[2*NPIX + p];
    float nrm = sqrtf(x0*x0 + x1*x1 + x2*x2);
    float den = fmaxf(nrm, 1e-12f);
    g_F[p*3+0] = x0/den; g_F[p*3+1] = x1/den; g_F[p*3+2] = x2/den;
}

__global__ void k_buildA(){
    __shared__ float sF[NPIX*3];
    __shared__ double red[256];
    int tid = threadIdx.x;
    for (int t = tid; t < NPIX*3; t += 256) sF[t] = g_F[t];
    __syncthreads();
    int i = blockIdx.x;
    float f0 = sF[3*i], f1 = sF[3*i+1], f2 = sF[3*i+2];
    float* rowp = g_A + (size_t)i*NPIX;
    double acc = 0.0;
    for (int j = tid; j < NPIX; j += 256){
        float s = f0*sF[3*j] + f1*sF[3*j+1] + f2*sF[3*j+2];
        s = (s > 0.f) ? s : 0.f;
        rowp[j] = s;
        acc += (double)s;
    }
    red[tid] = acc; __syncthreads();
    for (int s = 128; s > 0; s >>= 1){ if (tid < s) red[tid] += red[tid+s]; __syncthreads(); }
    if (tid == 0) g_deg[i] = red[0];   // W.max() scaling cancels in D^-1/2 W D^-1/2
}

__global__ void k_dinv(){
    int p = blockIdx.x*blockDim.x + threadIdx.x;
    if (p >= NPIX) return;
    g_dinv[p] = (float)(1.0/sqrt(g_deg[p]));   // deg >= 1 (diag is 1)
}

__global__ void k_scaleA(){
    int idx = blockIdx.x*blockDim.x + threadIdx.x;
    if (idx >= NPIX*NPIX) return;
    int i = idx / NPIX, j = idx % NPIX;
    g_A[idx] *= g_dinv[i]*g_dinv[j];
}

// -------- persistent Lanczos (CGS2, 5 grid barriers / iteration) ------------------
__global__ void k_reset(){ g_bar = 0u; }

__device__ __forceinline__ void gridbar(unsigned* step){
    __syncthreads();
    if (threadIdx.x == 0){
        unsigned tgt = (++(*step)) * (unsigned)NBLK;
        __threadfence();                       // release
        atomicAdd(&g_bar, 1u);
        while (*((volatile unsigned*)&g_bar) < tgt) { }   // pure spin, no nanosleep
        __threadfence();                       // acquire (CCTL.IVALL -> L1 refresh)
    }
    __syncthreads();
}

// deterministic per-block sum of squares -> g_nrm[bid]
__device__ __forceinline__ void blocknorm(float x, float* swred){
    int lane = threadIdx.x & 31, wip = threadIdx.x >> 5;
    float s = x;
    #pragma unroll
    for (int o = 16; o; o >>= 1) s += __shfl_down_sync(0xffffffffu, s, o);
    if (lane == 0) swred[wip] = s;
    __syncthreads();
    if (threadIdx.x == 0){
        float t = 0.f;
        #pragma unroll
        for (int i = 0; i < NTHR/32; i++) t += swred[i];
        g_nrm[blockIdx.x] = t;
    }
}

// warp-per-vector dots: cdst[i] = V[i] . src  (src staged in smem)
__device__ __forceinline__ void dotphase(int j, float* sw, const float* __restrict__ src,
                                         float* cdst, int bid, int tid, int lane, int gw){
    if (bid*(NTHR/32) <= j){
        for (int t = tid; t < NPIX; t += NTHR) sw[t] = src[t];
        __syncthreads();
        int i = gw;
        if (i <= j){
            const float2* vi  = (const float2*)(g_V + (size_t)i*NPIX);
            const float2* swv = (const float2*)sw;
            float acc = 0.f;
            #pragma unroll 5
            for (int k = 0; k < 25; k++){
                float2 a = vi[lane + 32*k];
                float2 b = swv[lane + 32*k];
                acc += a.x*b.x + a.y*b.y;
            }
            #pragma unroll
            for (int o = 16; o; o >>= 1) acc += __shfl_down_sync(0xffffffffu, acc, o);
            if (lane == 0) cdst[i] = acc;
        }
        __syncthreads();
    }
}

// fused stripe + apply:  dst[t] = base[t] - sum_{i<=j} c[i]*V[i][t]
// block b owns columns t = b*16 .. b*16+15; threads = (t_local, stripe).
// returns dst[t]^2 for the (s==0) threads, else 0 (for optional norm).
__device__ __forceinline__ float stripe_apply(int j, const float* __restrict__ cglob,
                                              const float* __restrict__ base,
                                              float* __restrict__ dst,
                                              float* sc, float (*sp)[TPB_T+1]){
    int bid = blockIdx.x, tid = threadIdx.x;
    float out = 0.f;
    if (bid < SBLK){
        for (int t = tid; t <= j; t += NTHR) sc[t] = cglob[t];
        __syncthreads();
        int tl = tid & (TPB_T-1);
        int s  = tid / TPB_T;
        int t  = bid*TPB_T + tl;
        int lo = s*ISTR;
        int hi = lo + ISTR; if (hi > j+1) hi = j+1;
        float acc = 0.f;
        if (hi == lo + ISTR){
            const float* vp = g_V + (size_t)lo*NPIX + t;
            #pragma unroll
            for (int i = 0; i < ISTR; i++) acc += sc[lo+i]*vp[(size_t)i*NPIX];
        } else {
            for (int i = lo; i < hi; i++) acc += sc[i]*g_V[(size_t)i*NPIX + t];
        }
        sp[s][tl] = acc;
        __syncthreads();
        if (s == 0){
            float v = base[t];
            #pragma unroll
            for (int k = 0; k < NSTR; k++) v -= sp[k][tl];
            dst[t] = v;
            out = v*v;
        }
        __syncthreads();
    }
    return out;
}

__global__ void __launch_bounds__(NTHR) k_lanczos(){
    __shared__ float sw[NPIX];
    __shared__ float sc[MLAN];
    __shared__ float sp[NSTR][TPB_T+1];
    __shared__ float swred[NTHR/32];
    __shared__ float sbinv;
    int tid = threadIdx.x, bid = blockIdx.x;
    int lane = tid & 31, wip = tid >> 5;
    int gw = bid*(NTHR/32) + wip;      // global warp 0..1023
    int gt = bid*NTHR + tid;           // global thread 0..32767
    unsigned bstep = 0;

    // ---- init random w0 + its per-block norm partials ----
    float x = 0.f;
    if (gt < NPIX){
        unsigned u = (unsigned)gt*2654435761u + 1234567u;
        u ^= u >> 13; u *= 2246822519u; u ^= u >> 16;
        float v = ((float)(u & 0x7FFFFF))/4194304.0f - 1.0f;
        g_w0[gt] = v;
        x = v*v;
    }
    blocknorm(x, swred);
    gridbar(&bstep);

    for (int j = 0; j < MLAN; j++){
        const float* wI = (j & 1) ? g_w1 : g_w0;
        float*       wN = (j & 1) ? g_w0 : g_w1;

        // ---- P1: beta_j, v_j = w/beta, w2 = (I - A) v_j ----
        if (tid == 0){
            double s = 0.0;
            #pragma unroll 8
            for (int i = 0; i < NBLK; i++) s += (double)g_nrm[i];
            float beta = (float)sqrt(s);
            if (beta < 1e-30f) beta = 1e-30f;
            sbinv = 1.0f/beta;
            if (bid == 0) g_betaA[j] = beta;
        }
        for (int t = tid; t < NPIX; t += NTHR) sw[t] = wI[t];
        __syncthreads();
        float binv = sbinv;
        if (gt < NPIX) g_V[(size_t)j*NPIX + gt] = sw[gt]*binv;
        for (int r = gw; r < NPIX; r += NWARP){
            const float2* row = (const float2*)(g_A + (size_t)r*NPIX);
            const float2* swv = (const float2*)sw;
            float acc = 0.f;
            #pragma unroll 5
            for (int k = 0; k < 25; k++){
                float2 a = row[lane + 32*k];
                float2 b = swv[lane + 32*k];
                acc += a.x*b.x + a.y*b.y;
            }
            #pragma unroll
            for (int o = 16; o; o >>= 1) acc += __shfl_down_sync(0xffffffffu, acc, o);
            if (lane == 0) g_w2[r] = (sw[r] - acc)*binv;
        }
        gridbar(&bstep);

        // ---- P2: reorth pass-1 dots: c1 = V^T w2 ----
        dotphase(j, sw, g_w2, g_c1, bid, tid, lane, gw);
        gridbar(&bstep);

        // ---- P3: fused stripe+apply pass 1: u1 = w2 - V c1 ----
        stripe_apply(j, g_c1, g_w2, g_u1, sc, sp);
        gridbar(&bstep);

        // ---- P4: reorth pass-2 dots: c2 = V^T u1 ----
        dotphase(j, sw, g_u1, g_c2, bid, tid, lane, gw);
        gridbar(&bstep);

        // ---- P5: fused stripe+apply pass 2: w_next = u1 - V c2; norm; alpha ----
        float xx = stripe_apply(j, g_c2, g_u1, wN, sc, sp);
        blocknorm(xx, swred);
        if (gt == 0) g_alphaA[j] = g_c1[j] + g_c2[j];
        gridbar(&bstep);
    }
}

// -------- tridiagonal bottom-K via Sturm multisection -----------------------------
__device__ __forceinline__ int sturm_count(float lam, const float* a, const float* b){
    float d = a[0] - lam;
    if (d == 0.f) d = -1e-25f;
    int c = (d < 0.f);
    for (int i = 1; i < MLAN; i++){
        d = (a[i] - lam) - (b[i]*b[i])/d;
        if (d == 0.f) d = -1e-25f;
        c += (d < 0.f);
    }
    return c;
}

__global__ void k_trieig(){
    __shared__ float sa[MLAN], sb[MLAN];
    __shared__ int   scnt[1024];
    __shared__ float sblo[KEIG], sbhi[KEIG];
    __shared__ float slo, shi;
    int tid = threadIdx.x;
    for (int i = tid; i < MLAN; i += 1024){
        sa[i] = g_alphaA[i];
        sb[i] = (i == 0) ? 0.f : g_betaA[i];  // sb[i] couples (i-1,i)
    }
    __syncthreads();
    if (tid == 0){
        float lo = 1e30f, hi = -1e30f;
        for (int i = 0; i < MLAN; i++){
            float r = fabsf(sb[i]) + ((i+1 < MLAN) ? fabsf(sb[i+1]) : 0.f);
            lo = fminf(lo, sa[i] - r);
            hi = fmaxf(hi, sa[i] + r);
        }
        slo = lo - 1e-4f; shi = hi + 1e-4f;
    }
    __syncthreads();
    {
        float lam = slo + (shi - slo)*((float)tid/1023.f);
        scnt[tid] = sturm_count(lam, sa, sb);
    }
    __syncthreads();
    if (tid < KEIG){
        int k = tid, tl = 0;
        for (int t = 1; t < 1024; t++) if (scnt[t] <= k) tl = t;
        sblo[k] = slo + (shi - slo)*((float)tl/1023.f);
        sbhi[k] = slo + (shi - slo)*((float)(tl+1)/1023.f);
    }
    __syncthreads();
    for (int round = 0; round < 3; round++){
        int k = tid/100, g = tid%100;
        if (tid < 1000){
            float lam = sblo[k] + (sbhi[k] - sblo[k])*((float)(g+1)/101.f);
            scnt[tid] = sturm_count(lam, sa, sb);
        }
        __syncthreads();
        if (tid < KEIG){
            int k2 = tid, gl = -1;
            for (int g2 = 0; g2 < 100; g2++) if (scnt[k2*100 + g2] <= k2) gl = g2;
            float lo = sblo[k2], w = sbhi[k2] - lo;
            sblo[k2] = lo + w*((float)(gl+1)/101.f);
            sbhi[k2] = lo + w*((float)(gl+2)/101.f);
        }
        __syncthreads();
    }
    if (tid < KEIG) g_lan3[tid] = 0.5f*(sblo[tid] + sbhi[tid]);
}

// -------- final loss ---------------------------------------------------------------
__global__ void k_loss(float* __restrict__ out){
    if (blockIdx.x == 0 && threadIdx.x == 0){
        double s12 = 0.0, s13 = 0.0, s23 = 0.0;
        for (int b = 0; b < NB; b++){
            for (int k = 0; k < KEIG; k++){
                double l1 = (double)g_lan12[b*KEIG + k];
                double l2 = (double)g_lan12[NB*KEIG + b*KEIG + k];
                double l3 = (double)g_lan3[k];
                double d;
                d = l1 - l2; s12 += d*d;
                d = l1 - l3; s13 += d*d;
                d = l2 - l3; s23 += d*d;
            }
        }
        out[0] = (float)(5.0*((s12 + s13 + s23)/(double)(NB*KEIG)));
    }
}

// -------- launch (11 graph nodes total) ---------------------------------------------
extern "C" void kernel_launch(void* const* d_in, const int* in_sizes, int n_in,
                              void* d_out, int out_size){
    const float* feats = (const float*)d_in[0];
    (void)in_sizes; (void)n_in; (void)out_size;   // K = 10, shapes fixed

    k_ds_h<<<(NB*NCH*HH*NH + 255)/256, 256>>>(feats);
    k_ds_v<<<(NB*NCH*NH*NH + 255)/256, 256>>>();
    k_signs<<<2*NB, 256>>>();

    k_buildF<<<(NPIX + 255)/256, 256>>>();
    k_buildA<<<NPIX, 256>>>();
    k_dinv<<<(NPIX + 255)/256, 256>>>();
    k_scaleA<<<(NPIX*NPIX + 255)/256, 256>>>();

    k_reset<<<1, 1>>>();
    k_lanczos<<<NBLK, NTHR>>>();
    k_trieig<<<1, 1024>>>();
    k_loss<<<1, 32>>>((float*)d_out);
}

// round 12
// speedup vs baseline: 5.4766x; 3.9619x over previous
#include <cuda_runtime.h>
#include <stdint.h>

#define NB    8
#define NCH   3
#define HH    160
#define NH    40
#define NPIX  1600     // 40*40
#define KEIG  10
#define MLAN  128      // Lanczos depth
#define NBLK  100      // persistent blocks, block b owns cols/rows 16b..16b+15
#define NTHR  512
#define TPB   16       // columns (and matvec rows) per block

// ---------------- device scratch (static globals; no allocation) ----------------
static __device__ float  g_t1[NB*NCH*HH*NH];      // width-downsampled
static __device__ float  g_ds[NB*NCH*NPIX];       // fully downsampled
static __device__ float  g_F[NPIX*3];             // normalized 3-vectors (batch 0)
static __device__ float  g_A[NPIX*NPIX];          // D^-1/2 W D^-1/2
static __device__ double g_deg[NPIX];
static __device__ float  g_dinv[NPIX];
static __device__ float  g_w[NPIX];               // residual vector (single buffer)
static __device__ float  g_P1[MLAN*NBLK];         // dots pass-1 partials [i][b]
static __device__ float  g_P2[MLAN*NBLK];         // dots pass-2 partials [i][b]
static __device__ float  g_nrm[NBLK];             // per-block norm^2 partials
static __device__ float  g_alphaA[MLAN];
static __device__ float  g_betaA[MLAN+1];
static __device__ unsigned g_bar;                 // software grid barrier counter
static __device__ float  g_lan12[2*NB*KEIG];
static __device__ float  g_lan3[KEIG];

__constant__ float c_bw[8] = {1.f,3.f,5.f,7.f,7.f,5.f,3.f,1.f};

// ---------------- downsample: jax.image.resize(bilinear, antialias=True), 4x ----
__global__ void k_ds_h(const float* __restrict__ feats){
    int idx = blockIdx.x*blockDim.x + threadIdx.x;
    if (idx >= NB*NCH*HH*NH) return;
    int ox = idx % NH;
    int y  = (idx / NH) % HH;
    int bc = idx / (NH*HH);
    const float* row = feats + ((size_t)bc*HH + y)*HH;
    int j0 = 4*ox - 2;
    float acc = 0.f, ws = 0.f;
    #pragma unroll
    for (int t = 0; t < 8; t++){
        int j = j0 + t;
        if (j >= 0 && j < HH){ acc += c_bw[t]*row[j]; ws += c_bw[t]; }
    }
    g_t1[idx] = acc/ws;
}

__global__ void k_ds_v(){
    int idx = blockIdx.x*blockDim.x + threadIdx.x;
    if (idx >= NB*NCH*NH*NH) return;
    int ox = idx % NH;
    int oy = (idx / NH) % NH;
    int bc = idx / (NH*NH);
    int j0 = 4*oy - 2;
    float acc = 0.f, ws = 0.f;
    #pragma unroll
    for (int t = 0; t < 8; t++){
        int j = j0 + t;
        if (j >= 0 && j < HH){ acc += c_bw[t]*g_t1[((size_t)bc*HH + j)*NH + ox]; ws += c_bw[t]; }
    }
    g_ds[idx] = acc/ws;
}

// -------- lan1/lan2 (C=1): spectrum exactly {0 per nonempty sign class, 1 rest} --
__global__ void k_signs(){
    __shared__ int sp[256], sn[256];
    int blk = blockIdx.x;           // 0..15
    int b = blk >> 1, ch = blk & 1;
    int tid = threadIdx.x;
    const float* base = g_ds + (size_t)(b*NCH + ch)*NPIX;
    int cp = 0, cn = 0;
    for (int p = tid; p < NPIX; p += 256){
        float x = base[p];
        cp += (x > 0.f); cn += (x < 0.f);
    }
    sp[tid] = cp; sn[tid] = cn; __syncthreads();
    for (int s = 128; s > 0; s >>= 1){
        if (tid < s){ sp[tid] += sp[tid+s]; sn[tid] += sn[tid+s]; }
        __syncthreads();
    }
    if (tid == 0){
        int ncomp = (sp[0] > 0) + (sn[0] > 0);
        float* lan = g_lan12 + ch*NB*KEIG + b*KEIG;
        for (int k = 0; k < KEIG; k++) lan[k] = (k < ncomp) ? 0.f : 1.f;
    }
}

// -------- lan3 path: batch 0, all 3 channels ------------------------------------
__global__ void k_buildF(){
    int p = blockIdx.x*blockDim.x + threadIdx.x;
    if (p >= NPIX) return;
    float x0 = g_ds[p], x1 = g_ds[NPIX + p], x2 = g_ds[2*NPIX + p];
    float nrm = sqrtf(x0*x0 + x1*x1 + x2*x2);
    float den = fmaxf(nrm, 1e-12f);
    g_F[p*3+0] = x0/den; g_F[p*3+1] = x1/den; g_F[p*3+2] = x2/den;
}

__global__ void k_buildA(){
    __shared__ float sF[NPIX*3];
    __shared__ double red[256];
    int tid = threadIdx.x;
    for (int t = tid; t < NPIX*3; t += 256) sF[t] = g_F[t];
    __syncthreads();
    int i = blockIdx.x;
    float f0 = sF[3*i], f1 = sF[3*i+1], f2 = sF[3*i+2];
    float* rowp = g_A + (size_t)i*NPIX;
    double acc = 0.0;
    for (int j = tid; j < NPIX; j += 256){
        float s = f0*sF[3*j] + f1*sF[3*j+1] + f2*sF[3*j+2];
        s = (s > 0.f) ? s : 0.f;
        rowp[j] = s;
        acc += (double)s;
    }
    red[tid] = acc; __syncthreads();
    for (int s = 128; s > 0; s >>= 1){ if (tid < s) red[tid] += red[tid+s]; __syncthreads(); }
    if (tid == 0) g_deg[i] = red[0];   // W.max() scaling cancels in D^-1/2 W D^-1/2
}

__global__ void k_dinv(){
    int p = blockIdx.x*blockDim.x + threadIdx.x;
    if (p >= NPIX) return;
    g_dinv[p] = (float)(1.0/sqrt(g_deg[p]));   // deg >= 1 (diag is 1)
}

__global__ void k_scaleA(){
    int idx = blockIdx.x*blockDim.x + threadIdx.x;
    if (idx >= NPIX*NPIX) return;
    int i = idx / NPIX, j = idx % NPIX;
    g_A[idx] *= g_dinv[i]*g_dinv[j];
}

// -------- persistent Lanczos (CGS2, 3 grid barriers / iteration) ------------------
__global__ void k_reset(){ g_bar = 0u; }

__device__ __forceinline__ void gridbar(unsigned* step){
    __syncthreads();
    if (threadIdx.x == 0){
        unsigned tgt = (++(*step)) * (unsigned)NBLK;
        __threadfence();                       // release
        atomicAdd(&g_bar, 1u);
        while (*((volatile unsigned*)&g_bar) < tgt) { }
        __threadfence();                       // acquire
    }
    __syncthreads();
}

__global__ void __launch_bounds__(NTHR) k_lanczos(){
    __shared__ float Vt[MLAN][TPB+1];   // persistent per-block V slice (own 16 cols)
    __shared__ float sv[NPIX];          // staged v_j (full vector)
    __shared__ float sw2[TPB];          // (I-A)v_j on own cols
    __shared__ float su1[TPB];          // after reorth pass 1, own cols
    __shared__ float sc1[MLAN], sc2[MLAN];
    __shared__ float sp[32][TPB+1];     // apply-phase stripe partials
    __shared__ float sred[NTHR/32];
    __shared__ float sbinv;
    int tid = threadIdx.x, b = blockIdx.x;
    int lane = tid & 31, w = tid >> 5;  // w = warp id 0..15
    int col0 = b*TPB;
    unsigned bstep = 0;

    // zero V tile (avoid NaN*0 from undefined smem when i>j in apply loops)
    for (int t = tid; t < MLAN*(TPB+1); t += NTHR) ((float*)Vt)[t] = 0.f;

    // ---- init: own 16 cols of random w + per-block norm partial ----
    if (tid < TPB){
        int p = col0 + tid;
        unsigned u = (unsigned)p*2654435761u + 1234567u;
        u ^= u >> 13; u *= 2246822519u; u ^= u >> 16;
        float v = ((float)(u & 0x7FFFFF))/4194304.0f - 1.0f;
        g_w[p] = v;
        float s = v*v;
        #pragma unroll
        for (int o = 8; o; o >>= 1) s += __shfl_down_sync(0xffffu, s, o);
        if (tid == 0) g_nrm[b] = s;
    }
    gridbar(&bstep);

    for (int j = 0; j < MLAN; j++){
        // ======== Phase A: beta, stage v_j, V append, matvec own rows, dots1 ====
        {   // parallel deterministic beta reduction (4 warps)
            float x = (tid < NBLK) ? g_nrm[tid] : 0.f;
            if (tid < 128){
                #pragma unroll
                for (int o = 16; o; o >>= 1) x += __shfl_down_sync(0xffffffffu, x, o);
                if (lane == 0) sred[w] = x;
            }
            __syncthreads();
            if (tid == 0){
                float s = sred[0] + sred[1] + sred[2] + sred[3];
                float beta = sqrtf(s);
                if (beta < 1e-30f) beta = 1e-30f;
                sbinv = 1.f/beta;
                if (b == 0) g_betaA[j] = beta;
            }
            __syncthreads();
        }
        float binv = sbinv;
        for (int t = tid; t < NPIX; t += NTHR) sv[t] = g_w[t]*binv;
        __syncthreads();
        if (tid < TPB) Vt[j][tid] = sv[col0 + tid];
        {   // matvec: warp w computes row r = col0 + w  (own rows == own cols)
            int r = col0 + w;
            const float2* row = (const float2*)(g_A + (size_t)r*NPIX);
            const float2* svv = (const float2*)sv;
            float acc = 0.f;
            #pragma unroll
            for (int k = 0; k < 25; k++){
                float2 a = row[lane + 32*k];
                float2 c = svv[lane + 32*k];
                acc += a.x*c.x + a.y*c.y;
            }
            #pragma unroll
            for (int o = 16; o; o >>= 1) acc += __shfl_down_sync(0xffffffffu, acc, o);
            if (lane == 0) sw2[w] = sv[r] - acc;   // (I - A) v_j, own rows
        }
        __syncthreads();
        // dots1 partials: P1[i][b] = sum_t Vt[i][t]*sw2[t]
        if (tid <= j){
            float a = 0.f;
            #pragma unroll
            for (int t = 0; t < TPB; t++) a += Vt[tid][t]*sw2[t];
            g_P1[tid*NBLK + b] = a;
        }
        gridbar(&bstep);

        // ======== Phase C: c1 = reduce(P1); u1 = w2 - V c1; dots2 partials =======
        if (tid < MLAN){
            float s = 0.f;
            if (tid <= j){
                const float* p = g_P1 + tid*NBLK;
                #pragma unroll 10
                for (int bb = 0; bb < NBLK; bb++) s += p[bb];
            }
            sc1[tid] = s;
        }
        __syncthreads();
        {
            int tl = tid & (TPB-1), s32 = tid/TPB;     // s32: 0..31
            float a = 0.f;
            #pragma unroll
            for (int q = 0; q < MLAN/32; q++){
                int i = s32*(MLAN/32) + q;
                a += sc1[i]*Vt[i][tl];
            }
            sp[s32][tl] = a;
            __syncthreads();
            if (tid < TPB){
                float v = sw2[tid];
                #pragma unroll
                for (int k = 0; k < 32; k++) v -= sp[k][tid];
                su1[tid] = v;
            }
            __syncthreads();
        }
        if (tid <= j){
            float a = 0.f;
            #pragma unroll
            for (int t = 0; t < TPB; t++) a += Vt[tid][t]*su1[t];
            g_P2[tid*NBLK + b] = a;
        }
        gridbar(&bstep);

        // ======== Phase D: c2 = reduce(P2); w_next = u1 - V c2; norm; alpha ======
        if (tid < MLAN){
            float s = 0.f;
            if (tid <= j){
                const float* p = g_P2 + tid*NBLK;
                #pragma unroll 10
                for (int bb = 0; bb < NBLK; bb++) s += p[bb];
            }
            sc2[tid] = s;
        }
        __syncthreads();
        {
            int tl = tid & (TPB-1), s32 = tid/TPB;
            float a = 0.f;
            #pragma unroll
            for (int q = 0; q < MLAN/32; q++){
                int i = s32*(MLAN/32) + q;
                a += sc2[i]*Vt[i][tl];
            }
            sp[s32][tl] = a;
            __syncthreads();
            if (tid < TPB){
                float v = su1[tid];
                #pragma unroll
                for (int k = 0; k < 32; k++) v -= sp[k][tid];
                g_w[col0 + tid] = v;
                float s = v*v;
                #pragma unroll
                for (int o = 8; o; o >>= 1) s += __shfl_down_sync(0xffffu, s, o);
                if (tid == 0) g_nrm[b] = s;
            }
            if (b == 0 && tid == 0) g_alphaA[j] = sc1[j] + sc2[j];
        }
        gridbar(&bstep);
    }
}

// -------- tridiagonal bottom-K via Sturm multisection -----------------------------
__device__ __forceinline__ int sturm_count(float lam, const float* a, const float* b){
    float d = a[0] - lam;
    if (d == 0.f) d = -1e-25f;
    int c = (d < 0.f);
    for (int i = 1; i < MLAN; i++){
        d = (a[i] - lam) - __fdividef(b[i]*b[i], d);
        if (d == 0.f) d = -1e-25f;
        c += (d < 0.f);
    }
    return c;
}

__global__ void k_trieig(){
    __shared__ float sa[MLAN], sb[MLAN];
    __shared__ int   scnt[1024];
    __shared__ float sblo[KEIG], sbhi[KEIG];
    __shared__ float slo, shi;
    int tid = threadIdx.x;
    for (int i = tid; i < MLAN; i += 1024){
        sa[i] = g_alphaA[i];
        sb[i] = (i == 0) ? 0.f : g_betaA[i];  // sb[i] couples (i-1,i)
    }
    __syncthreads();
    if (tid == 0){
        float lo = 1e30f, hi = -1e30f;
        for (int i = 0; i < MLAN; i++){
            float r = fabsf(sb[i]) + ((i+1 < MLAN) ? fabsf(sb[i+1]) : 0.f);
            lo = fminf(lo, sa[i] - r);
            hi = fmaxf(hi, sa[i] + r);
        }
        slo = lo - 1e-4f; shi = hi + 1e-4f;
    }
    __syncthreads();
    {
        float lam = slo + (shi - slo)*((float)tid/1023.f);
        scnt[tid] = sturm_count(lam, sa, sb);
    }
    __syncthreads();
    if (tid < KEIG){
        int k = tid, tl = 0;
        for (int t = 1; t < 1024; t++) if (scnt[t] <= k) tl = t;
        sblo[k] = slo + (shi - slo)*((float)tl/1023.f);
        sbhi[k] = slo + (shi - slo)*((float)(tl+1)/1023.f);
    }
    __syncthreads();
    for (int round = 0; round < 3; round++){
        int k = tid/100, g = tid%100;
        if (tid < 1000){
            float lam = sblo[k] + (sbhi[k] - sblo[k])*((float)(g+1)/101.f);
            scnt[tid] = sturm_count(lam, sa, sb);
        }
        __syncthreads();
        if (tid < KEIG){
            int k2 = tid, gl = -1;
            for (int g2 = 0; g2 < 100; g2++) if (scnt[k2*100 + g2] <= k2) gl = g2;
            float lo = sblo[k2], w = sbhi[k2] - lo;
            sblo[k2] = lo + w*((float)(gl+1)/101.f);
            sbhi[k2] = lo + w*((float)(gl+2)/101.f);
        }
        __syncthreads();
    }
    if (tid < KEIG) g_lan3[tid] = 0.5f*(sblo[tid] + sbhi[tid]);
}

// -------- final loss ---------------------------------------------------------------
__global__ void k_loss(float* __restrict__ out){
    if (blockIdx.x == 0 && threadIdx.x == 0){
        double s12 = 0.0, s13 = 0.0, s23 = 0.0;
        for (int b = 0; b < NB; b++){
            for (int k = 0; k < KEIG; k++){
                double l1 = (double)g_lan12[b*KEIG + k];
                double l2 = (double)g_lan12[NB*KEIG + b*KEIG + k];
                double l3 = (double)g_lan3[k];
                double d;
                d = l1 - l2; s12 += d*d;
                d = l1 - l3; s13 += d*d;
                d = l2 - l3; s23 += d*d;
            }
        }
        out[0] = (float)(5.0*((s12 + s13 + s23)/(double)(NB*KEIG)));
    }
}

// -------- launch (11 graph nodes total) ---------------------------------------------
extern "C" void kernel_launch(void* const* d_in, const int* in_sizes, int n_in,
                              void* d_out, int out_size){
    const float* feats = (const float*)d_in[0];
    (void)in_sizes; (void)n_in; (void)out_size;   // K = 10, shapes fixed

    k_ds_h<<<(NB*NCH*HH*NH + 255)/256, 256>>>(feats);
    k_ds_v<<<(NB*NCH*NH*NH + 255)/256, 256>>>();
    k_signs<<<2*NB, 256>>>();

    k_buildF<<<(NPIX + 255)/256, 256>>>();
    k_buildA<<<NPIX, 256>>>();
    k_dinv<<<(NPIX + 255)/256, 256>>>();
    k_scaleA<<<(NPIX*NPIX + 255)/256, 256>>>();

    k_reset<<<1, 1>>>();
    k_lanczos<<<NBLK, NTHR>>>();
    k_trieig<<<1, 1024>>>();
    k_loss<<<1, 32>>>((float*)d_out);
}

// round 13
// speedup vs baseline: 9.7839x; 1.7865x over previous
#include <cuda_runtime.h>
#include <stdint.h>

#define NB    8
#define NCH   3
#define HH    160
#define NH    40
#define NPIX  1600     // 40*40
#define KEIG  10
#define MLAN  96       // Lanczos depth (m=128 was converged with big margin)
#define NBLK  100      // persistent blocks, block b owns cols/rows 16b..16b+15
#define NTHR  512
#define TPB   16       // columns (and matvec rows) per block

// ---------------- device scratch (static globals; no allocation) ----------------
static __device__ float  g_t1[NB*NCH*HH*NH];      // width-downsampled
static __device__ float  g_ds[NB*NCH*NPIX];       // fully downsampled
static __device__ float  g_F[NPIX*3];             // normalized 3-vectors (batch 0)
static __device__ float  g_A[NPIX*NPIX];          // D^-1/2 W D^-1/2
static __device__ double g_deg[NPIX];
static __device__ float  g_dinv[NPIX];
static __device__ float  g_w[NPIX];               // residual vector
static __device__ float  g_P1[NBLK*MLAN];         // dots pass-1 partials [b][i]
static __device__ float  g_P2[NBLK*MLAN];         // dots pass-2 partials [b][i]
static __device__ float  g_nrm[NBLK];             // per-block norm^2 partials
static __device__ float  g_alphaA[MLAN];
static __device__ float  g_betaA[MLAN+1];
static __device__ unsigned g_bar;                 // software grid barrier counter
static __device__ float  g_lan12[2*NB*KEIG];
static __device__ float  g_lan3[KEIG];

__constant__ float c_bw[8] = {1.f,3.f,5.f,7.f,7.f,5.f,3.f,1.f};

// ---------------- downsample: jax.image.resize(bilinear, antialias=True), 4x ----
__global__ void k_ds_h(const float* __restrict__ feats){
    int idx = blockIdx.x*blockDim.x + threadIdx.x;
    if (idx >= NB*NCH*HH*NH) return;
    int ox = idx % NH;
    int y  = (idx / NH) % HH;
    int bc = idx / (NH*HH);
    const float* row = feats + ((size_t)bc*HH + y)*HH;
    int j0 = 4*ox - 2;
    float acc = 0.f, ws = 0.f;
    #pragma unroll
    for (int t = 0; t < 8; t++){
        int j = j0 + t;
        if (j >= 0 && j < HH){ acc += c_bw[t]*row[j]; ws += c_bw[t]; }
    }
    g_t1[idx] = acc/ws;
}

__global__ void k_ds_v(){
    int idx = blockIdx.x*blockDim.x + threadIdx.x;
    if (idx >= NB*NCH*NH*NH) return;
    int ox = idx % NH;
    int oy = (idx / NH) % NH;
    int bc = idx / (NH*NH);
    int j0 = 4*oy - 2;
    float acc = 0.f, ws = 0.f;
    #pragma unroll
    for (int t = 0; t < 8; t++){
        int j = j0 + t;
        if (j >= 0 && j < HH){ acc += c_bw[t]*g_t1[((size_t)bc*HH + j)*NH + ox]; ws += c_bw[t]; }
    }
    g_ds[idx] = acc/ws;
}

// -------- lan1/lan2 (C=1): spectrum exactly {0 per nonempty sign class, 1 rest} --
__global__ void k_signs(){
    __shared__ int sp[256], sn[256];
    int blk = blockIdx.x;           // 0..15
    int b = blk >> 1, ch = blk & 1;
    int tid = threadIdx.x;
    const float* base = g_ds + (size_t)(b*NCH + ch)*NPIX;
    int cp = 0, cn = 0;
    for (int p = tid; p < NPIX; p += 256){
        float x = base[p];
        cp += (x > 0.f); cn += (x < 0.f);
    }
    sp[tid] = cp; sn[tid] = cn; __syncthreads();
    for (int s = 128; s > 0; s >>= 1){
        if (tid < s){ sp[tid] += sp[tid+s]; sn[tid] += sn[tid+s]; }
        __syncthreads();
    }
    if (tid == 0){
        int ncomp = (sp[0] > 0) + (sn[0] > 0);
        float* lan = g_lan12 + ch*NB*KEIG + b*KEIG;
        for (int k = 0; k < KEIG; k++) lan[k] = (k < ncomp) ? 0.f : 1.f;
    }
}

// -------- lan3 path: batch 0, all 3 channels ------------------------------------
__global__ void k_buildF(){
    int p = blockIdx.x*blockDim.x + threadIdx.x;
    if (p >= NPIX) return;
    float x0 = g_ds[p], x1 = g_ds[NPIX + p], x2 = g_ds[2*NPIX + p];
    float nrm = sqrtf(x0*x0 + x1*x1 + x2*x2);
    float den = fmaxf(nrm, 1e-12f);
    g_F[p*3+0] = x0/den; g_F[p*3+1] = x1/den; g_F[p*3+2] = x2/den;
}

__global__ void k_buildA(){
    __shared__ float sF[NPIX*3];
    __shared__ double red[256];
    int tid = threadIdx.x;
    for (int t = tid; t < NPIX*3; t += 256) sF[t] = g_F[t];
    __syncthreads();
    int i = blockIdx.x;
    float f0 = sF[3*i], f1 = sF[3*i+1], f2 = sF[3*i+2];
    float* rowp = g_A + (size_t)i*NPIX;
    double acc = 0.0;
    for (int j = tid; j < NPIX; j += 256){
        float s = f0*sF[3*j] + f1*sF[3*j+1] + f2*sF[3*j+2];
        s = (s > 0.f) ? s : 0.f;
        rowp[j] = s;
        acc += (double)s;
    }
    red[tid] = acc; __syncthreads();
    for (int s = 128; s > 0; s >>= 1){ if (tid < s) red[tid] += red[tid+s]; __syncthreads(); }
    if (tid == 0) g_deg[i] = red[0];   // W.max() scaling cancels in D^-1/2 W D^-1/2
}

__global__ void k_dinv(){
    int p = blockIdx.x*blockDim.x + threadIdx.x;
    if (p >= NPIX) return;
    g_dinv[p] = (float)(1.0/sqrt(g_deg[p]));   // deg >= 1 (diag is 1)
}

__global__ void k_scaleA(){
    int idx = blockIdx.x*blockDim.x + threadIdx.x;
    if (idx >= NPIX*NPIX) return;
    int i = idx / NPIX, j = idx % NPIX;
    g_A[idx] *= g_dinv[i]*g_dinv[j];
}

// -------- persistent Lanczos (CGS2, 3 grid barriers / iteration) ------------------
__global__ void k_reset(){ g_bar = 0u; }

__device__ __forceinline__ void gridbar(unsigned* step){
    __syncthreads();
    if (threadIdx.x == 0){
        unsigned tgt = (++(*step)) * (unsigned)NBLK;
        __threadfence();                       // release
        atomicAdd(&g_bar, 1u);
        while (*((volatile unsigned*)&g_bar) < tgt) { }
        __threadfence();                       // acquire
    }
    __syncthreads();
}

// coalesced deterministic reduce: sc[i] = sum_b P[b*MLAN + i]  (i<=j), else 0
__device__ __forceinline__ void reduceP(const float* __restrict__ P, float* sc,
                                        float (*s4)[MLAN], int j, int tid){
    int q = tid / MLAN;            // 0..5 (only q<4 active)
    int i = tid - q*MLAN;
    if (q < 4){
        float s = 0.f;
        if (i <= j){
            const float* p = P + (size_t)q*25*MLAN + i;
            #pragma unroll
            for (int bb = 0; bb < 25; bb++) s += p[(size_t)bb*MLAN];
        }
        s4[q][i] = s;
    }
    __syncthreads();
    if (tid < MLAN) sc[tid] = (s4[0][tid] + s4[1][tid]) + (s4[2][tid] + s4[3][tid]);
    __syncthreads();
}

__global__ void __launch_bounds__(NTHR) k_lanczos(){
    __shared__ float Vt[MLAN][TPB+1];   // persistent per-block V slice (own 16 cols)
    __shared__ float sv[NPIX];          // staged v_j (full vector)
    __shared__ float sw2[TPB];          // (I-A)v_j on own cols
    __shared__ float su1[TPB];          // after reorth pass 1, own cols
    __shared__ float sc1[MLAN], sc2[MLAN];
    __shared__ float s4[4][MLAN];       // reduce partials
    __shared__ float sp[32][TPB+1];     // apply-phase stripe partials
    __shared__ float sred[NTHR/32];
    __shared__ float sbinv;
    int tid = threadIdx.x, b = blockIdx.x;
    int lane = tid & 31, w = tid >> 5;  // w = warp id 0..15
    int col0 = b*TPB;
    unsigned bstep = 0;

    // zero V tile (avoid garbage*0 in apply loops for i>j)
    for (int t = tid; t < MLAN*(TPB+1); t += NTHR) ((float*)Vt)[t] = 0.f;

    // ---- init: own 16 cols of random w + per-block norm partial ----
    if (tid < TPB){
        int p = col0 + tid;
        unsigned u = (unsigned)p*2654435761u + 1234567u;
        u ^= u >> 13; u *= 2246822519u; u ^= u >> 16;
        float v = ((float)(u & 0x7FFFFF))/4194304.0f - 1.0f;
        g_w[p] = v;
        float s = v*v;
        #pragma unroll
        for (int o = 8; o; o >>= 1) s += __shfl_down_sync(0xffffu, s, o);
        if (tid == 0) g_nrm[b] = s;
    }
    gridbar(&bstep);

    for (int j = 0; j < MLAN; j++){
        // ======== Phase A: beta, stage v_j, V append, matvec own rows, dots1 ====
        {   // parallel deterministic beta reduction
            float x = (tid < NBLK) ? g_nrm[tid] : 0.f;
            if (tid < 128){
                #pragma unroll
                for (int o = 16; o; o >>= 1) x += __shfl_down_sync(0xffffffffu, x, o);
                if (lane == 0) sred[w] = x;
            }
            __syncthreads();
            if (tid == 0){
                float s = sred[0] + sred[1] + sred[2] + sred[3];
                float beta = sqrtf(s);
                if (beta < 1e-30f) beta = 1e-30f;
                sbinv = 1.f/beta;
                if (b == 0) g_betaA[j] = beta;
            }
            __syncthreads();
        }
        float binv = sbinv;
        for (int t = tid; t < NPIX; t += NTHR) sv[t] = g_w[t]*binv;
        __syncthreads();
        if (tid < TPB) Vt[j][tid] = sv[col0 + tid];
        {   // matvec: warp w computes row r = col0 + w  (own rows == own cols)
            int r = col0 + w;
            const float2* row = (const float2*)(g_A + (size_t)r*NPIX);
            const float2* svv = (const float2*)sv;
            float acc = 0.f;
            #pragma unroll
            for (int k = 0; k < 25; k++){
                float2 a = row[lane + 32*k];
                float2 c = svv[lane + 32*k];
                acc += a.x*c.x + a.y*c.y;
            }
            #pragma unroll
            for (int o = 16; o; o >>= 1) acc += __shfl_down_sync(0xffffffffu, acc, o);
            if (lane == 0) sw2[w] = sv[r] - acc;   // (I - A) v_j, own rows
        }
        __syncthreads();
        // dots1 partials: P1[b][i] = sum_t Vt[i][t]*sw2[t]  (coalesced write)
        if (tid <= j){
            float a = 0.f;
            #pragma unroll
            for (int t = 0; t < TPB; t++) a += Vt[tid][t]*sw2[t];
            g_P1[(size_t)b*MLAN + tid] = a;
        }
        gridbar(&bstep);

        // ======== Phase C: c1 = reduce(P1); u1 = w2 - V c1; dots2 partials =======
        reduceP(g_P1, sc1, s4, j, tid);
        {
            int tl = tid & (TPB-1), s32 = tid/TPB;     // s32: 0..31
            float a = 0.f;
            #pragma unroll
            for (int q = 0; q < MLAN/32; q++){
                int i = s32*(MLAN/32) + q;
                a += sc1[i]*Vt[i][tl];
            }
            sp[s32][tl] = a;
            __syncthreads();
            if (tid < TPB){
                float v = sw2[tid];
                #pragma unroll
                for (int k = 0; k < 32; k++) v -= sp[k][tid];
                su1[tid] = v;
            }
            __syncthreads();
        }
        if (tid <= j){
            float a = 0.f;
            #pragma unroll
            for (int t = 0; t < TPB; t++) a += Vt[tid][t]*su1[t];
            g_P2[(size_t)b*MLAN + tid] = a;
        }
        gridbar(&bstep);

        // ======== Phase D: c2 = reduce(P2); w_next = u1 - V c2; norm; alpha ======
        reduceP(g_P2, sc2, s4, j, tid);
        {
            int tl = tid & (TPB-1), s32 = tid/TPB;
            float a = 0.f;
            #pragma unroll
            for (int q = 0; q < MLAN/32; q++){
                int i = s32*(MLAN/32) + q;
                a += sc2[i]*Vt[i][tl];
            }
            sp[s32][tl] = a;
            __syncthreads();
            if (tid < TPB){
                float v = su1[tid];
                #pragma unroll
                for (int k = 0; k < 32; k++) v -= sp[k][tid];
                g_w[col0 + tid] = v;
                float s = v*v;
                #pragma unroll
                for (int o = 8; o; o >>= 1) s += __shfl_down_sync(0xffffu, s, o);
                if (tid == 0) g_nrm[b] = s;
            }
            if (b == 0 && tid == 0) g_alphaA[j] = sc1[j] + sc2[j];
        }
        gridbar(&bstep);
    }
}

// -------- tridiagonal bottom-K via Sturm multisection -----------------------------
__device__ __forceinline__ int sturm_count(float lam, const float* a, const float* b){
    float d = a[0] - lam;
    if (d == 0.f) d = -1e-25f;
    int c = (d < 0.f);
    for (int i = 1; i < MLAN; i++){
        d = (a[i] - lam) - __fdividef(b[i]*b[i], d);
        if (d == 0.f) d = -1e-25f;
        c += (d < 0.f);
    }
    return c;
}

__global__ void k_trieig(){
    __shared__ float sa[MLAN], sb[MLAN];
    __shared__ int   scnt[1024];
    __shared__ float sblo[KEIG], sbhi[KEIG];
    __shared__ float slo, shi;
    int tid = threadIdx.x;
    for (int i = tid; i < MLAN; i += 1024){
        sa[i] = g_alphaA[i];
        sb[i] = (i == 0) ? 0.f : g_betaA[i];  // sb[i] couples (i-1,i)
    }
    __syncthreads();
    if (tid == 0){
        float lo = 1e30f, hi = -1e30f;
        for (int i = 0; i < MLAN; i++){
            float r = fabsf(sb[i]) + ((i+1 < MLAN) ? fabsf(sb[i+1]) : 0.f);
            lo = fminf(lo, sa[i] - r);
            hi = fmaxf(hi, sa[i] + r);
        }
        slo = lo - 1e-4f; shi = hi + 1e-4f;
    }
    __syncthreads();
    {
        float lam = slo + (shi - slo)*((float)tid/1023.f);
        scnt[tid] = sturm_count(lam, sa, sb);
    }
    __syncthreads();
    if (tid < KEIG){
        int k = tid, tl = 0;
        for (int t = 1; t < 1024; t++) if (scnt[t] <= k) tl = t;
        sblo[k] = slo + (shi - slo)*((float)tl/1023.f);
        sbhi[k] = slo + (shi - slo)*((float)(tl+1)/1023.f);
    }
    __syncthreads();
    for (int round = 0; round < 3; round++){
        int k = tid/100, g = tid%100;
        if (tid < 1000){
            float lam = sblo[k] + (sbhi[k] - sblo[k])*((float)(g+1)/101.f);
            scnt[tid] = sturm_count(lam, sa, sb);
        }
        __syncthreads();
        if (tid < KEIG){
            int k2 = tid, gl = -1;
            for (int g2 = 0; g2 < 100; g2++) if (scnt[k2*100 + g2] <= k2) gl = g2;
            float lo = sblo[k2], w = sbhi[k2] - lo;
            sblo[k2] = lo + w*((float)(gl+1)/101.f);
            sbhi[k2] = lo + w*((float)(gl+2)/101.f);
        }
        __syncthreads();
    }
    if (tid < KEIG) g_lan3[tid] = 0.5f*(sblo[tid] + sbhi[tid]);
}

// -------- final loss ---------------------------------------------------------------
__global__ void k_loss(float* __restrict__ out){
    if (blockIdx.x == 0 && threadIdx.x == 0){
        double s12 = 0.0, s13 = 0.0, s23 = 0.0;
        for (int b = 0; b < NB; b++){
            for (int k = 0; k < KEIG; k++){
                double l1 = (double)g_lan12[b*KEIG + k];
                double l2 = (double)g_lan12[NB*KEIG + b*KEIG + k];
                double l3 = (double)g_lan3[k];
                double d;
                d = l1 - l2; s12 += d*d;
                d = l1 - l3; s13 += d*d;
                d = l2 - l3; s23 += d*d;
            }
        }
        out[0] = (float)(5.0*((s12 + s13 + s23)/(double)(NB*KEIG)));
    }
}

// -------- launch (11 graph nodes total) ---------------------------------------------
extern "C" void kernel_launch(void* const* d_in, const int* in_sizes, int n_in,
                              void* d_out, int out_size){
    const float* feats = (const float*)d_in[0];
    (void)in_sizes; (void)n_in; (void)out_size;   // K = 10, shapes fixed

    k_ds_h<<<(NB*NCH*HH*NH + 255)/256, 256>>>(feats);
    k_ds_v<<<(NB*NCH*NH*NH + 255)/256, 256>>>();
    k_signs<<<2*NB, 256>>>();

    k_buildF<<<(NPIX + 255)/256, 256>>>();
    k_buildA<<<NPIX, 256>>>();
    k_dinv<<<(NPIX + 255)/256, 256>>>();
    k_scaleA<<<(NPIX*NPIX + 255)/256, 256>>>();

    k_reset<<<1, 1>>>();
    k_lanczos<<<NBLK, NTHR>>>();
    k_trieig<<<1, 1024>>>();
    k_loss<<<1, 32>>>((float*)d_out);
}

// round 15
// speedup vs baseline: 17.8879x; 1.8283x over previous
#include <cuda_runtime.h>
#include <stdint.h>

#define NB    8
#define NCH   3
#define HH    160
#define NH    40
#define NPIX  1600     // 40*40
#define KEIG  10
#define MLAN  64       // Lanczos depth (96 was converged with large margin)
#define NBLK  100      // persistent blocks, block b owns cols/rows 16b..16b+15
#define NTHR  512
#define TPB   16       // columns (and matvec rows) per block

// ---------------- device scratch (static globals; no allocation) ----------------
static __device__ float  g_t1[NB*NCH*HH*NH];      // width-downsampled
static __device__ float  g_ds[NB*NCH*NPIX];       // fully downsampled
static __device__ float  g_F[NPIX*3];             // normalized 3-vectors (batch 0)
static __device__ float  g_A[NPIX*NPIX];          // D^-1/2 W D^-1/2
static __device__ float  g_dinv[NPIX];
static __device__ float  g_w[NPIX];               // residual vector
static __device__ float  g_P1[NBLK*MLAN];         // dots pass-1 partials [b][i]
static __device__ float  g_P2[NBLK*MLAN];         // dots pass-2 partials [b][i]
static __device__ float  g_nrm[NBLK];             // per-block norm^2 partials
static __device__ float  g_alphaA[MLAN];
static __device__ float  g_betaA[MLAN+1];
static __device__ unsigned g_bar;                 // software grid barrier counter
static __device__ float  g_lan12[2*NB*KEIG];

__constant__ float c_bw[8] = {1.f,3.f,5.f,7.f,7.f,5.f,3.f,1.f};

// ---------------- downsample: jax.image.resize(bilinear, antialias=True), 4x ----
__global__ void k_ds_h(const float* __restrict__ feats){
    int idx = blockIdx.x*blockDim.x + threadIdx.x;
    if (idx >= NB*NCH*HH*NH) return;
    int ox = idx % NH;
    int y  = (idx / NH) % HH;
    int bc = idx / (NH*HH);
    const float* row = feats + ((size_t)bc*HH + y)*HH;
    int j0 = 4*ox - 2;
    float acc = 0.f, ws = 0.f;
    #pragma unroll
    for (int t = 0; t < 8; t++){
        int j = j0 + t;
        if (j >= 0 && j < HH){ acc += c_bw[t]*row[j]; ws += c_bw[t]; }
    }
    g_t1[idx] = acc/ws;
}

__global__ void k_ds_v(){
    int idx = blockIdx.x*blockDim.x + threadIdx.x;
    if (idx >= NB*NCH*NH*NH) return;
    int ox = idx % NH;
    int oy = (idx / NH) % NH;
    int bc = idx / (NH*NH);
    int j0 = 4*oy - 2;
    float acc = 0.f, ws = 0.f;
    #pragma unroll
    for (int t = 0; t < 8; t++){
        int j = j0 + t;
        if (j >= 0 && j < HH){ acc += c_bw[t]*g_t1[((size_t)bc*HH + j)*NH + ox]; ws += c_bw[t]; }
    }
    g_ds[idx] = acc/ws;
}

// -------- merged: lan1/lan2 sign-count (blocks 0..15) + buildF (blocks 16..22) ----
__global__ void k_post(){
    int blk = blockIdx.x;
    int tid = threadIdx.x;
    if (blk < 16){
        // lan1/lan2 (C=1): spectrum exactly {0 per nonempty sign class, 1 rest}
        __shared__ int sp[256], sn[256];
        int b = blk >> 1, ch = blk & 1;
        const float* base = g_ds + (size_t)(b*NCH + ch)*NPIX;
        int cp = 0, cn = 0;
        for (int p = tid; p < NPIX; p += 256){
            float x = base[p];
            cp += (x > 0.f); cn += (x < 0.f);
        }
        sp[tid] = cp; sn[tid] = cn; __syncthreads();
        for (int s = 128; s > 0; s >>= 1){
            if (tid < s){ sp[tid] += sp[tid+s]; sn[tid] += sn[tid+s]; }
            __syncthreads();
        }
        if (tid == 0){
            int ncomp = (sp[0] > 0) + (sn[0] > 0);
            float* lan = g_lan12 + ch*NB*KEIG + b*KEIG;
            for (int k = 0; k < KEIG; k++) lan[k] = (k < ncomp) ? 0.f : 1.f;
        }
    } else {
        // buildF: normalized 3-vectors for batch 0
        int p = (blk - 16)*256 + tid;
        if (p < NPIX){
            float x0 = g_ds[p], x1 = g_ds[NPIX + p], x2 = g_ds[2*NPIX + p];
            float nrm = sqrtf(x0*x0 + x1*x1 + x2*x2);
            float den = fmaxf(nrm, 1e-12f);
            g_F[p*3+0] = x0/den; g_F[p*3+1] = x1/den; g_F[p*3+2] = x2/den;
        }
    }
}

// -------- affinity row + degree + dinv (fused) ------------------------------------
__global__ void k_buildA(){
    __shared__ float sF[NPIX*3];
    __shared__ double red[256];
    int tid = threadIdx.x;
    for (int t = tid; t < NPIX*3; t += 256) sF[t] = g_F[t];
    __syncthreads();
    int i = blockIdx.x;
    float f0 = sF[3*i], f1 = sF[3*i+1], f2 = sF[3*i+2];
    float* rowp = g_A + (size_t)i*NPIX;
    double acc = 0.0;
    for (int j = tid; j < NPIX; j += 256){
        float s = f0*sF[3*j] + f1*sF[3*j+1] + f2*sF[3*j+2];
        s = (s > 0.f) ? s : 0.f;
        rowp[j] = s;
        acc += (double)s;
    }
    red[tid] = acc; __syncthreads();
    for (int s = 128; s > 0; s >>= 1){ if (tid < s) red[tid] += red[tid+s]; __syncthreads(); }
    // W.max() scaling cancels in D^-1/2 W D^-1/2 ; deg >= 1 (diag is 1)
    if (tid == 0) g_dinv[i] = (float)(1.0/sqrt(red[0]));
}

__global__ void k_scaleA(){
    int idx = blockIdx.x*blockDim.x + threadIdx.x;
    if (idx >= NPIX*NPIX) return;
    int i = idx / NPIX, j = idx % NPIX;
    g_A[idx] *= g_dinv[i]*g_dinv[j];
}

// -------- persistent Lanczos (CGS2, 3 grid barriers / iteration) ------------------
__global__ void k_reset(){ g_bar = 0u; }

// Release: red.release.gpu orders this block's prior stores at GPU scope
// (no CCTL.IVALL — unlike __threadfence).
// Acquire: ld.acquire.gpu spin with "memory" clobber orders subsequent loads
// (the cooperative-groups grid.sync() pattern). Cross-block data reads all
// use __ldcg (L2-direct) so stale L1 lines are structurally impossible.
__device__ __forceinline__ void gridbar(unsigned* step){
    __syncthreads();
    if (threadIdx.x == 0){
        unsigned tgt = (++(*step)) * (unsigned)NBLK;
        asm volatile("red.release.gpu.global.add.u32 [%0], %1;"
                     :: "l"(&g_bar), "r"(1u) : "memory");
        unsigned v;
        do {
            asm volatile("ld.acquire.gpu.global.u32 %0, [%1];"
                         : "=r"(v) : "l"(&g_bar) : "memory");
        } while (v < tgt);
    }
    __syncthreads();
}

// coalesced deterministic reduce: sc[i] = sum_b P[b*MLAN + i]  (i<=j), else 0
__device__ __forceinline__ void reduceP(const float* __restrict__ P, float* sc,
                                        float (*s4)[MLAN], int j, int tid){
    int q = tid / MLAN;
    int i = tid - q*MLAN;
    if (q < 4){
        float s = 0.f;
        if (i <= j){
            const float* p = P + (size_t)q*25*MLAN + i;
            #pragma unroll
            for (int bb = 0; bb < 25; bb++) s += __ldcg(p + (size_t)bb*MLAN);
        }
        s4[q][i] = s;
    }
    __syncthreads();
    if (tid < MLAN) sc[tid] = (s4[0][tid] + s4[1][tid]) + (s4[2][tid] + s4[3][tid]);
    __syncthreads();
}

__global__ void __launch_bounds__(NTHR) k_lanczos(){
    __shared__ float Vt[MLAN][TPB+1];   // persistent per-block V slice (own 16 cols)
    __shared__ float sv[NPIX];          // staged v_j (full vector)
    __shared__ float sw2[TPB];          // (I-A)v_j on own cols
    __shared__ float su1[TPB];          // after reorth pass 1, own cols
    __shared__ float sc1[MLAN], sc2[MLAN];
    __shared__ float s4[4][MLAN];       // reduce partials
    __shared__ float sp[32][TPB+1];     // apply-phase stripe partials
    __shared__ float sred[NTHR/32];
    __shared__ float sbinv;
    int tid = threadIdx.x, b = blockIdx.x;
    int lane = tid & 31, w = tid >> 5;  // w = warp id 0..15
    int col0 = b*TPB;
    unsigned bstep = 0;

    // zero V tile (avoid garbage*0 in apply loops for i>j)
    for (int t = tid; t < MLAN*(TPB+1); t += NTHR) ((float*)Vt)[t] = 0.f;

    // ---- init: own 16 cols of random w + per-block norm partial ----
    if (tid < TPB){
        int p = col0 + tid;
        unsigned u = (unsigned)p*2654435761u + 1234567u;
        u ^= u >> 13; u *= 2246822519u; u ^= u >> 16;
        float v = ((float)(u & 0x7FFFFF))/4194304.0f - 1.0f;
        g_w[p] = v;
        float s = v*v;
        #pragma unroll
        for (int o = 8; o; o >>= 1) s += __shfl_down_sync(0xffffu, s, o);
        if (tid == 0) g_nrm[b] = s;
    }
    gridbar(&bstep);

    for (int j = 0; j < MLAN; j++){
        // ======== Phase A: beta, stage v_j, V append, matvec own rows, dots1 ====
        {   // parallel deterministic beta reduction
            float x = (tid < NBLK) ? __ldcg(&g_nrm[tid]) : 0.f;
            if (tid < 128){
                #pragma unroll
                for (int o = 16; o; o >>= 1) x += __shfl_down_sync(0xffffffffu, x, o);
                if (lane == 0) sred[w] = x;
            }
            __syncthreads();
            if (tid == 0){
                float s = sred[0] + sred[1] + sred[2] + sred[3];
                float beta = sqrtf(s);
                if (beta < 1e-30f) beta = 1e-30f;
                sbinv = 1.f/beta;
                if (b == 0) g_betaA[j] = beta;
            }
            __syncthreads();
        }
        float binv = sbinv;
        for (int t = tid; t < NPIX; t += NTHR) sv[t] = __ldcg(&g_w[t])*binv;
        __syncthreads();
        if (tid < TPB) Vt[j][tid] = sv[col0 + tid];
        {   // matvec: warp w computes row r = col0 + w  (own rows == own cols)
            int r = col0 + w;
            const float2* row = (const float2*)(g_A + (size_t)r*NPIX);
            const float2* svv = (const float2*)sv;
            float acc = 0.f;
            #pragma unroll
            for (int k = 0; k < 25; k++){
                float2 a = row[lane + 32*k];
                float2 c = svv[lane + 32*k];
                acc += a.x*c.x + a.y*c.y;
            }
            #pragma unroll
            for (int o = 16; o; o >>= 1) acc += __shfl_down_sync(0xffffffffu, acc, o);
            if (lane == 0) sw2[w] = sv[r] - acc;   // (I - A) v_j, own rows
        }
        __syncthreads();
        // dots1 partials: P1[b][i] = sum_t Vt[i][t]*sw2[t]  (coalesced write)
        if (tid <= j){
            float a = 0.f;
            #pragma unroll
            for (int t = 0; t < TPB; t++) a += Vt[tid][t]*sw2[t];
            g_P1[(size_t)b*MLAN + tid] = a;
        }
        gridbar(&bstep);

        // ======== Phase C: c1 = reduce(P1); u1 = w2 - V c1; dots2 partials =======
        reduceP(g_P1, sc1, s4, j, tid);
        {
            int tl = tid & (TPB-1), s32 = tid/TPB;     // s32: 0..31
            float a = 0.f;
            #pragma unroll
            for (int q = 0; q < MLAN/32; q++){
                int i = s32*(MLAN/32) + q;
                a += sc1[i]*Vt[i][tl];
            }
            sp[s32][tl] = a;
            __syncthreads();
            if (tid < TPB){
                float v = sw2[tid];
                #pragma unroll
                for (int k = 0; k < 32; k++) v -= sp[k][tid];
                su1[tid] = v;
            }
            __syncthreads();
        }
        if (tid <= j){
            float a = 0.f;
            #pragma unroll
            for (int t = 0; t < TPB; t++) a += Vt[tid][t]*su1[t];
            g_P2[(size_t)b*MLAN + tid] = a;
        }
        gridbar(&bstep);

        // ======== Phase D: c2 = reduce(P2); w_next = u1 - V c2; norm; alpha ======
        reduceP(g_P2, sc2, s4, j, tid);
        {
            int tl = tid & (TPB-1), s32 = tid/TPB;
            float a = 0.f;
            #pragma unroll
            for (int q = 0; q < MLAN/32; q++){
                int i = s32*(MLAN/32) + q;
                a += sc2[i]*Vt[i][tl];
            }
            sp[s32][tl] = a;
            __syncthreads();
            if (tid < TPB){
                float v = su1[tid];
                #pragma unroll
                for (int k = 0; k < 32; k++) v -= sp[k][tid];
                g_w[col0 + tid] = v;
                float s = v*v;
                #pragma unroll
                for (int o = 8; o; o >>= 1) s += __shfl_down_sync(0xffffu, s, o);
                if (tid == 0) g_nrm[b] = s;
            }
            if (b == 0 && tid == 0) g_alphaA[j] = sc1[j] + sc2[j];
        }
        gridbar(&bstep);
    }
}

// -------- tridiagonal bottom-K via Sturm multisection + final loss ------------------
__device__ __forceinline__ int sturm_count(float lam, const float* a, const float* b){
    float d = a[0] - lam;
    if (d == 0.f) d = -1e-25f;
    int c = (d < 0.f);
    for (int i = 1; i < MLAN; i++){
        d = (a[i] - lam) - __fdividef(b[i]*b[i], d);
        if (d == 0.f) d = -1e-25f;
        c += (d < 0.f);
    }
    return c;
}

__global__ void k_trieig(float* __restrict__ out){
    __shared__ float sa[MLAN], sb[MLAN];
    __shared__ int   scnt[1024];
    __shared__ float sblo[KEIG], sbhi[KEIG];
    __shared__ float slo, shi;
    int tid = threadIdx.x;
    if (tid < MLAN){
        sa[tid] = g_alphaA[tid];
        sb[tid] = (tid == 0) ? 0.f : g_betaA[tid];  // sb[i] couples (i-1,i)
    }
    __syncthreads();
    if (tid == 0){
        float lo = 1e30f, hi = -1e30f;
        for (int i = 0; i < MLAN; i++){
            float r = fabsf(sb[i]) + ((i+1 < MLAN) ? fabsf(sb[i+1]) : 0.f);
            lo = fminf(lo, sa[i] - r);
            hi = fmaxf(hi, sa[i] + r);
        }
        slo = lo - 1e-4f; shi = hi + 1e-4f;
    }
    __syncthreads();
    {
        float lam = slo + (shi - slo)*((float)tid/1023.f);
        scnt[tid] = sturm_count(lam, sa, sb);
    }
    __syncthreads();
    if (tid < KEIG){
        int k = tid, tl = 0;
        for (int t = 1; t < 1024; t++) if (scnt[t] <= k) tl = t;
        sblo[k] = slo + (shi - slo)*((float)tl/1023.f);
        sbhi[k] = slo + (shi - slo)*((float)(tl+1)/1023.f);
    }
    __syncthreads();
    for (int round = 0; round < 2; round++){
        int k = tid/100, g = tid%100;
        if (tid < 1000){
            float lam = sblo[k] + (sbhi[k] - sblo[k])*((float)(g+1)/101.f);
            scnt[tid] = sturm_count(lam, sa, sb);
        }
        __syncthreads();
        if (tid < KEIG){
            int k2 = tid, gl = -1;
            for (int g2 = 0; g2 < 100; g2++) if (scnt[k2*100 + g2] <= k2) gl = g2;
            float lo = sblo[k2], w = sbhi[k2] - lo;
            sblo[k2] = lo + w*((float)(gl+1)/101.f);
            sbhi[k2] = lo + w*((float)(gl+2)/101.f);
        }
        __syncthreads();
    }
    // final loss (single thread; lan3[k] = midpoint of bracket k)
    if (tid == 0){
        double s12 = 0.0, s13 = 0.0, s23 = 0.0;
        for (int b = 0; b < NB; b++){
            for (int k = 0; k < KEIG; k++){
                double l1 = (double)g_lan12[b*KEIG + k];
                double l2 = (double)g_lan12[NB*KEIG + b*KEIG + k];
                double l3 = 0.5*((double)sblo[k] + (double)sbhi[k]);
                double d;
                d = l1 - l2; s12 += d*d;
                d = l1 - l3; s13 += d*d;
                d = l2 - l3; s23 += d*d;
            }
        }
        out[0] = (float)(5.0*((s12 + s13 + s23)/(double)(NB*KEIG)));
    }
}

// -------- launch (8 graph nodes total) ----------------------------------------------
extern "C" void kernel_launch(void* const* d_in, const int* in_sizes, int n_in,
                              void* d_out, int out_size){
    const float* feats = (const float*)d_in[0];
    (void)in_sizes; (void)n_in; (void)out_size;   // K = 10, shapes fixed

    k_ds_h<<<(NB*NCH*HH*NH + 255)/256, 256>>>(feats);
    k_ds_v<<<(NB*NCH*NH*NH + 255)/256, 256>>>();
    k_post<<<16 + (NPIX + 255)/256, 256>>>();     // signs + buildF
    k_buildA<<<NPIX, 256>>>();                    // rows + dinv fused
    k_scaleA<<<(NPIX*NPIX + 255)/256, 256>>>();

    k_reset<<<1, 1>>>();
    k_lanczos<<<NBLK, NTHR>>>();
    k_trieig<<<1, 1024>>>((float*)d_out);         // eig + loss fused
}

// round 16
// speedup vs baseline: 22.8987x; 1.2801x over previous
#include <cuda_runtime.h>
#include <stdint.h>

#define NB    8
#define NCH   3
#define HH    160
#define NH    40
#define NPIX  1600     // 40*40
#define KEIG  10
#define MLAN  48       // Lanczos iterations actually run
#define MLANP 64       // padded depth for array sizing / stripe loops
#define NBLK  100      // persistent blocks, block b owns cols/rows 16b..16b+15
#define NTHR  512
#define TPB   16       // columns (and matvec rows) per block

// ---------------- device scratch (static globals; no allocation) ----------------
static __device__ float  g_t1[NB*NCH*HH*NH];      // width-downsampled
static __device__ float  g_ds[NB*NCH*NPIX];       // fully downsampled
static __device__ float  g_F[NPIX*3];             // normalized 3-vectors (batch 0)
static __device__ float  g_A[NPIX*NPIX];          // W (unscaled relu affinity)
static __device__ float  g_dinv[NPIX];
static __device__ float  g_w[NPIX];               // residual vector
static __device__ float  g_P1[NBLK*MLANP];        // dots pass-1 partials [b][i]
static __device__ float  g_P2[NBLK*MLANP];        // dots pass-2 partials [b][i]
static __device__ float  g_nrm[NBLK];             // per-block norm^2 partials
static __device__ float  g_alphaA[MLANP];
static __device__ float  g_betaA[MLANP+1];
static __device__ unsigned g_bar;                 // software grid barrier counter
static __device__ float  g_lan12[2*NB*KEIG];

__constant__ float c_bw[8] = {1.f,3.f,5.f,7.f,7.f,5.f,3.f,1.f};

// ---------------- downsample: jax.image.resize(bilinear, antialias=True), 4x ----
__global__ void k_ds_h(const float* __restrict__ feats){
    int idx = blockIdx.x*blockDim.x + threadIdx.x;
    if (idx >= NB*NCH*HH*NH) return;
    int ox = idx % NH;
    int y  = (idx / NH) % HH;
    int bc = idx / (NH*HH);
    const float* row = feats + ((size_t)bc*HH + y)*HH;
    int j0 = 4*ox - 2;
    float acc = 0.f, ws = 0.f;
    #pragma unroll
    for (int t = 0; t < 8; t++){
        int j = j0 + t;
        if (j >= 0 && j < HH){ acc += c_bw[t]*row[j]; ws += c_bw[t]; }
    }
    g_t1[idx] = acc/ws;
}

__global__ void k_ds_v(){
    int idx = blockIdx.x*blockDim.x + threadIdx.x;
    if (idx >= NB*NCH*NH*NH) return;
    int ox = idx % NH;
    int oy = (idx / NH) % NH;
    int bc = idx / (NH*NH);
    int j0 = 4*oy - 2;
    float acc = 0.f, ws = 0.f;
    #pragma unroll
    for (int t = 0; t < 8; t++){
        int j = j0 + t;
        if (j >= 0 && j < HH){ acc += c_bw[t]*g_t1[((size_t)bc*HH + j)*NH + ox]; ws += c_bw[t]; }
    }
    g_ds[idx] = acc/ws;
}

// -------- merged: lan1/lan2 sign-count (blocks 0..15) + buildF (blocks 16..22) ----
__global__ void k_post(){
    int blk = blockIdx.x;
    int tid = threadIdx.x;
    if (blk < 16){
        // lan1/lan2 (C=1): spectrum exactly {0 per nonempty sign class, 1 rest}
        __shared__ int sp[256], sn[256];
        int b = blk >> 1, ch = blk & 1;
        const float* base = g_ds + (size_t)(b*NCH + ch)*NPIX;
        int cp = 0, cn = 0;
        for (int p = tid; p < NPIX; p += 256){
            float x = base[p];
            cp += (x > 0.f); cn += (x < 0.f);
        }
        sp[tid] = cp; sn[tid] = cn; __syncthreads();
        for (int s = 128; s > 0; s >>= 1){
            if (tid < s){ sp[tid] += sp[tid+s]; sn[tid] += sn[tid+s]; }
            __syncthreads();
        }
        if (tid == 0){
            int ncomp = (sp[0] > 0) + (sn[0] > 0);
            float* lan = g_lan12 + ch*NB*KEIG + b*KEIG;
            for (int k = 0; k < KEIG; k++) lan[k] = (k < ncomp) ? 0.f : 1.f;
        }
    } else {
        // buildF: normalized 3-vectors for batch 0
        int p = (blk - 16)*256 + tid;
        if (p < NPIX){
            float x0 = g_ds[p], x1 = g_ds[NPIX + p], x2 = g_ds[2*NPIX + p];
            float nrm = sqrtf(x0*x0 + x1*x1 + x2*x2);
            float den = fmaxf(nrm, 1e-12f);
            g_F[p*3+0] = x0/den; g_F[p*3+1] = x1/den; g_F[p*3+2] = x2/den;
        }
    }
}

// -------- affinity W + degree + dinv: 100 blocks, warp-per-row ---------------------
__global__ void __launch_bounds__(NTHR) k_buildA(){
    __shared__ float sF[NPIX*3];
    int tid = threadIdx.x, b = blockIdx.x;
    int lane = tid & 31, w = tid >> 5;    // 16 warps, warp w -> row r = 16b + w
    for (int t = tid; t < NPIX*3; t += NTHR) sF[t] = g_F[t];
    __syncthreads();
    int r = b*TPB + w;
    float f0 = sF[3*r], f1 = sF[3*r+1], f2 = sF[3*r+2];
    float* rowp = g_A + (size_t)r*NPIX;
    float deg = 0.f;
    #pragma unroll 10
    for (int j = lane; j < NPIX; j += 32){
        float s = f0*sF[3*j] + f1*sF[3*j+1] + f2*sF[3*j+2];
        s = (s > 0.f) ? s : 0.f;
        rowp[j] = s;
        deg += s;
    }
    #pragma unroll
    for (int o = 16; o; o >>= 1) deg += __shfl_down_sync(0xffffffffu, deg, o);
    // W.max() scaling cancels in D^-1/2 W D^-1/2 ; deg >= 1 (diag is 1)
    if (lane == 0) g_dinv[r] = rsqrtf(deg);
}

// -------- persistent Lanczos (CGS2, 3 grid barriers / iteration) ------------------
__global__ void k_reset(){ g_bar = 0u; }

// Release: red.release.gpu orders prior stores at GPU scope (no CCTL.IVALL).
// Acquire: ld.acquire.gpu spin with "memory" clobber; cross-block data reads
// all use __ldcg (L2-direct) so stale L1 lines are structurally impossible.
__device__ __forceinline__ void gridbar(unsigned* step){
    __syncthreads();
    if (threadIdx.x == 0){
        unsigned tgt = (++(*step)) * (unsigned)NBLK;
        asm volatile("red.release.gpu.global.add.u32 [%0], %1;"
                     :: "l"(&g_bar), "r"(1u) : "memory");
        unsigned v;
        do {
            asm volatile("ld.acquire.gpu.global.u32 %0, [%1];"
                         : "=r"(v) : "l"(&g_bar) : "memory");
        } while (v < tgt);
    }
    __syncthreads();
}

// coalesced deterministic reduce: sc[i] = sum_b P[b*MLANP + i]  (i<=j), else 0
__device__ __forceinline__ void reduceP(const float* __restrict__ P, float* sc,
                                        float (*s4)[MLANP], int j, int tid){
    int q = tid / MLANP;
    int i = tid - q*MLANP;
    if (q < 4){
        float s = 0.f;
        if (i <= j){
            const float* p = P + (size_t)q*25*MLANP + i;
            #pragma unroll
            for (int bb = 0; bb < 25; bb++) s += __ldcg(p + (size_t)bb*MLANP);
        }
        s4[q][i] = s;
    }
    __syncthreads();
    if (tid < MLANP) sc[tid] = (s4[0][tid] + s4[1][tid]) + (s4[2][tid] + s4[3][tid]);
    __syncthreads();
}

__global__ void __launch_bounds__(NTHR) k_lanczos(){
    __shared__ float Vt[MLANP][TPB+1];  // persistent per-block V slice (own 16 cols)
    __shared__ __align__(16) float sv[NPIX];    // staged v_j
    __shared__ __align__(16) float svd[NPIX];   // dinv .* v_j
    __shared__ __align__(16) float sdinv[NPIX]; // staged dinv (loop-invariant)
    __shared__ float sw2[TPB];          // (I-A)v_j on own cols
    __shared__ float su1[TPB];          // after reorth pass 1, own cols
    __shared__ float sc1[MLANP], sc2[MLANP];
    __shared__ float s4[4][MLANP];      // reduce partials
    __shared__ float sp[32][TPB+1];     // apply-phase stripe partials
    __shared__ float sred[NTHR/32];
    __shared__ float sbinv;
    int tid = threadIdx.x, b = blockIdx.x;
    int lane = tid & 31, w = tid >> 5;  // w = warp id 0..15
    int col0 = b*TPB;
    unsigned bstep = 0;

    // zero V tile (avoid garbage*0 in apply loops for i>j)
    for (int t = tid; t < MLANP*(TPB+1); t += NTHR) ((float*)Vt)[t] = 0.f;
    // stage dinv once (constant during this kernel)
    for (int t = tid; t < NPIX; t += NTHR) sdinv[t] = g_dinv[t];

    // ---- init: own 16 cols of random w + per-block norm partial ----
    if (tid < TPB){
        int p = col0 + tid;
        unsigned u = (unsigned)p*2654435761u + 1234567u;
        u ^= u >> 13; u *= 2246822519u; u ^= u >> 16;
        float v = ((float)(u & 0x7FFFFF))/4194304.0f - 1.0f;
        g_w[p] = v;
        float s = v*v;
        #pragma unroll
        for (int o = 8; o; o >>= 1) s += __shfl_down_sync(0xffffu, s, o);
        if (tid == 0) g_nrm[b] = s;
    }
    gridbar(&bstep);

    for (int j = 0; j < MLAN; j++){
        // ======== Phase A: beta, stage v_j, V append, matvec own rows, dots1 ====
        {   // parallel deterministic beta reduction
            float x = (tid < NBLK) ? __ldcg(&g_nrm[tid]) : 0.f;
            if (tid < 128){
                #pragma unroll
                for (int o = 16; o; o >>= 1) x += __shfl_down_sync(0xffffffffu, x, o);
                if (lane == 0) sred[w] = x;
            }
            __syncthreads();
            if (tid == 0){
                float s = sred[0] + sred[1] + sred[2] + sred[3];
                float beta = sqrtf(s);
                if (beta < 1e-30f) beta = 1e-30f;
                sbinv = 1.f/beta;
                if (b == 0) g_betaA[j] = beta;
            }
            __syncthreads();
        }
        float binv = sbinv;
        for (int t = tid; t < NPIX; t += NTHR){
            float v = __ldcg(&g_w[t])*binv;
            sv[t]  = v;
            svd[t] = v*sdinv[t];
        }
        __syncthreads();
        if (tid < TPB) Vt[j][tid] = sv[col0 + tid];
        {   // matvec: warp w computes row r = col0 + w  (own rows == own cols)
            int r = col0 + w;
            const float2* row = (const float2*)(g_A + (size_t)r*NPIX);
            const float2* svv = (const float2*)svd;
            float acc = 0.f;
            #pragma unroll
            for (int k = 0; k < 25; k++){
                float2 a = row[lane + 32*k];
                float2 c = svv[lane + 32*k];
                acc += a.x*c.x + a.y*c.y;
            }
            #pragma unroll
            for (int o = 16; o; o >>= 1) acc += __shfl_down_sync(0xffffffffu, acc, o);
            if (lane == 0) sw2[w] = sv[r] - sdinv[r]*acc;   // (I - D^-1/2 W D^-1/2) v_j
        }
        __syncthreads();
        // dots1 partials: P1[b][i] = sum_t Vt[i][t]*sw2[t]  (coalesced write)
        if (tid <= j){
            float a = 0.f;
            #pragma unroll
            for (int t = 0; t < TPB; t++) a += Vt[tid][t]*sw2[t];
            g_P1[(size_t)b*MLANP + tid] = a;
        }
        gridbar(&bstep);

        // ======== Phase C: c1 = reduce(P1); u1 = w2 - V c1; dots2 partials =======
        reduceP(g_P1, sc1, s4, j, tid);
        {
            int tl = tid & (TPB-1), s32 = tid/TPB;     // s32: 0..31
            float a = 0.f;
            #pragma unroll
            for (int q = 0; q < MLANP/32; q++){
                int i = s32*(MLANP/32) + q;
                a += sc1[i]*Vt[i][tl];
            }
            sp[s32][tl] = a;
            __syncthreads();
            if (tid < TPB){
                float v = sw2[tid];
                #pragma unroll
                for (int k = 0; k < 32; k++) v -= sp[k][tid];
                su1[tid] = v;
            }
            __syncthreads();
        }
        if (tid <= j){
            float a = 0.f;
            #pragma unroll
            for (int t = 0; t < TPB; t++) a += Vt[tid][t]*su1[t];
            g_P2[(size_t)b*MLANP + tid] = a;
        }
        gridbar(&bstep);

        // ======== Phase D: c2 = reduce(P2); w_next = u1 - V c2; norm; alpha ======
        reduceP(g_P2, sc2, s4, j, tid);
        {
            int tl = tid & (TPB-1), s32 = tid/TPB;
            float a = 0.f;
            #pragma unroll
            for (int q = 0; q < MLANP/32; q++){
                int i = s32*(MLANP/32) + q;
                a += sc2[i]*Vt[i][tl];
            }
            sp[s32][tl] = a;
            __syncthreads();
            if (tid < TPB){
                float v = su1[tid];
                #pragma unroll
                for (int k = 0; k < 32; k++) v -= sp[k][tid];
                g_w[col0 + tid] = v;
                float s = v*v;
                #pragma unroll
                for (int o = 8; o; o >>= 1) s += __shfl_down_sync(0xffffu, s, o);
                if (tid == 0) g_nrm[b] = s;
            }
            if (b == 0 && tid == 0) g_alphaA[j] = sc1[j] + sc2[j];
        }
        gridbar(&bstep);
    }
}

// -------- tridiagonal bottom-K via Sturm multisection + final loss ------------------
__device__ __forceinline__ int sturm_count(float lam, const float* a, const float* b){
    float d = a[0] - lam;
    if (d == 0.f) d = -1e-25f;
    int c = (d < 0.f);
    for (int i = 1; i < MLAN; i++){
        d = (a[i] - lam) - __fdividef(b[i]*b[i], d);
        if (d == 0.f) d = -1e-25f;
        c += (d < 0.f);
    }
    return c;
}

__global__ void k_trieig(float* __restrict__ out){
    __shared__ float sa[MLAN], sb[MLAN];
    __shared__ int   scnt[1024];
    __shared__ float sblo[KEIG], sbhi[KEIG];
    __shared__ float slo, shi;
    int tid = threadIdx.x;
    if (tid < MLAN){
        sa[tid] = g_alphaA[tid];
        sb[tid] = (tid == 0) ? 0.f : g_betaA[tid];  // sb[i] couples (i-1,i)
    }
    __syncthreads();
    if (tid == 0){
        float lo = 1e30f, hi = -1e30f;
        for (int i = 0; i < MLAN; i++){
            float r = fabsf(sb[i]) + ((i+1 < MLAN) ? fabsf(sb[i+1]) : 0.f);
            lo = fminf(lo, sa[i] - r);
            hi = fmaxf(hi, sa[i] + r);
        }
        slo = lo - 1e-4f; shi = hi + 1e-4f;
    }
    __syncthreads();
    {
        float lam = slo + (shi - slo)*((float)tid/1023.f);
        scnt[tid] = sturm_count(lam, sa, sb);
    }
    __syncthreads();
    if (tid < KEIG){
        int k = tid, tl = 0;
        for (int t = 1; t < 1024; t++) if (scnt[t] <= k) tl = t;
        sblo[k] = slo + (shi - slo)*((float)tl/1023.f);
        sbhi[k] = slo + (shi - slo)*((float)(tl+1)/1023.f);
    }
    __syncthreads();
    for (int round = 0; round < 2; round++){
        int k = tid/100, g = tid%100;
        if (tid < 1000){
            float lam = sblo[k] + (sbhi[k] - sblo[k])*((float)(g+1)/101.f);
            scnt[tid] = sturm_count(lam, sa, sb);
        }
        __syncthreads();
        if (tid < KEIG){
            int k2 = tid, gl = -1;
            for (int g2 = 0; g2 < 100; g2++) if (scnt[k2*100 + g2] <= k2) gl = g2;
            float lo = sblo[k2], w = sbhi[k2] - lo;
            sblo[k2] = lo + w*((float)(gl+1)/101.f);
            sbhi[k2] = lo + w*((float)(gl+2)/101.f);
        }
        __syncthreads();
    }
    // final loss (single thread; lan3[k] = midpoint of bracket k)
    if (tid == 0){
        double s12 = 0.0, s13 = 0.0, s23 = 0.0;
        for (int b = 0; b < NB; b++){
            for (int k = 0; k < KEIG; k++){
                double l1 = (double)g_lan12[b*KEIG + k];
                double l2 = (double)g_lan12[NB*KEIG + b*KEIG + k];
                double l3 = 0.5*((double)sblo[k] + (double)sbhi[k]);
                double d;
                d = l1 - l2; s12 += d*d;
                d = l1 - l3; s13 += d*d;
                d = l2 - l3; s23 += d*d;
            }
        }
        out[0] = (float)(5.0*((s12 + s13 + s23)/(double)(NB*KEIG)));
    }
}

// -------- launch (7 graph nodes total) ----------------------------------------------
extern "C" void kernel_launch(void* const* d_in, const int* in_sizes, int n_in,
                              void* d_out, int out_size){
    const float* feats = (const float*)d_in[0];
    (void)in_sizes; (void)n_in; (void)out_size;   // K = 10, shapes fixed

    k_ds_h<<<(NB*NCH*HH*NH + 255)/256, 256>>>(feats);
    k_ds_v<<<(NB*NCH*NH*NH + 255)/256, 256>>>();
    k_post<<<16 + (NPIX + 255)/256, 256>>>();     // signs + buildF
    k_buildA<<<NBLK, NTHR>>>();                   // W rows + dinv (no scaleA pass)

    k_reset<<<1, 1>>>();
    k_lanczos<<<NBLK, NTHR>>>();
    k_trieig<<<1, 1024>>>((float*)d_out);         // eig + loss fused
}

// round 17
// speedup vs baseline: 32.0161x; 1.3982x over previous
#include <cuda_runtime.h>
#include <stdint.h>

#define NB    8
#define NCH   3
#define HH    160
#define NH    40
#define NPIX  1600     // 40*40
#define KEIG  10
#define MLAN  40       // Lanczos iterations actually run
#define MLANP 64       // padded depth for array sizing / stripe loops
#define NBLK  100      // persistent blocks, block b owns cols/rows 16b..16b+15
#define NTHR  512
#define TPB   16       // columns (and matvec rows) per block

// ---------------- device scratch (static globals; no allocation) ----------------
static __device__ float  g_ds[NB*NCH*NPIX];       // fully downsampled
static __device__ float  g_F[NPIX*3];             // normalized 3-vectors (batch 0)
static __device__ float  g_A[NPIX*NPIX];          // W (unscaled relu affinity)
static __device__ float  g_dinv[NPIX];
static __device__ __align__(16) float g_w[NPIX];  // residual vector
static __device__ float  g_P1[NBLK*MLANP];        // dots pass-1 partials [b][i]
static __device__ float  g_P2[NBLK*MLANP];        // dots pass-2 partials [b][i]
static __device__ float  g_nrm[NBLK];             // per-block norm^2 partials
static __device__ float  g_alphaA[MLANP];
static __device__ float  g_betaA[MLANP+1];
static __device__ unsigned g_bar;                 // software grid barrier counter
static __device__ float  g_lan12[2*NB*KEIG];

__constant__ float c_bw[8] = {1.f,3.f,5.f,7.f,7.f,5.f,3.f,1.f};

// ---- fused downsample: jax.image.resize(bilinear, antialias=True), 4x both axes --
// one block per (b,c) image; t1 intermediate lives in smem.
__global__ void k_ds(const float* __restrict__ feats){
    __shared__ float st1[HH*NH];     // 160x40 = 25.6 KB
    int bc = blockIdx.x, tid = threadIdx.x;
    const float* img = feats + (size_t)bc*HH*HH;
    for (int idx = tid; idx < HH*NH; idx += 256){
        int ox = idx % NH, y = idx / NH;
        int j0 = 4*ox - 2;
        float acc = 0.f, ws = 0.f;
        #pragma unroll
        for (int t = 0; t < 8; t++){
            int j = j0 + t;
            if (j >= 0 && j < HH){ acc += c_bw[t]*img[y*HH + j]; ws += c_bw[t]; }
        }
        st1[idx] = acc/ws;
    }
    __syncthreads();
    for (int idx = tid; idx < NH*NH; idx += 256){
        int ox = idx % NH, oy = idx / NH;
        int j0 = 4*oy - 2;
        float acc = 0.f, ws = 0.f;
        #pragma unroll
        for (int t = 0; t < 8; t++){
            int j = j0 + t;
            if (j >= 0 && j < HH){ acc += c_bw[t]*st1[j*NH + ox]; ws += c_bw[t]; }
        }
        g_ds[(size_t)bc*NPIX + idx] = acc/ws;
    }
}

// -------- merged: lan1/lan2 sign-count (blocks 0..15) + buildF (blocks 16..22) ----
__global__ void k_post(){
    int blk = blockIdx.x;
    int tid = threadIdx.x;
    if (blk < 16){
        // lan1/lan2 (C=1): spectrum exactly {0 per nonempty sign class, 1 rest}
        __shared__ int sp[256], sn[256];
        int b = blk >> 1, ch = blk & 1;
        const float* base = g_ds + (size_t)(b*NCH + ch)*NPIX;
        int cp = 0, cn = 0;
        for (int p = tid; p < NPIX; p += 256){
            float x = base[p];
            cp += (x > 0.f); cn += (x < 0.f);
        }
        sp[tid] = cp; sn[tid] = cn; __syncthreads();
        for (int s = 128; s > 0; s >>= 1){
            if (tid < s){ sp[tid] += sp[tid+s]; sn[tid] += sn[tid+s]; }
            __syncthreads();
        }
        if (tid == 0){
            int ncomp = (sp[0] > 0) + (sn[0] > 0);
            float* lan = g_lan12 + ch*NB*KEIG + b*KEIG;
            for (int k = 0; k < KEIG; k++) lan[k] = (k < ncomp) ? 0.f : 1.f;
        }
    } else {
        // buildF: normalized 3-vectors for batch 0
        int p = (blk - 16)*256 + tid;
        if (p < NPIX){
            float x0 = g_ds[p], x1 = g_ds[NPIX + p], x2 = g_ds[2*NPIX + p];
            float nrm = sqrtf(x0*x0 + x1*x1 + x2*x2);
            float den = fmaxf(nrm, 1e-12f);
            g_F[p*3+0] = x0/den; g_F[p*3+1] = x1/den; g_F[p*3+2] = x2/den;
        }
    }
}

// -------- affinity W + degree + dinv: 100 blocks, warp-per-row ---------------------
__global__ void __launch_bounds__(NTHR) k_buildA(){
    __shared__ float sF[NPIX*3];
    int tid = threadIdx.x, b = blockIdx.x;
    int lane = tid & 31, w = tid >> 5;    // 16 warps, warp w -> row r = 16b + w
    if (b == 0 && tid == 0) g_bar = 0u;   // barrier reset for k_lanczos
    for (int t = tid; t < NPIX*3; t += NTHR) sF[t] = g_F[t];
    __syncthreads();
    int r = b*TPB + w;
    float f0 = sF[3*r], f1 = sF[3*r+1], f2 = sF[3*r+2];
    float* rowp = g_A + (size_t)r*NPIX;
    float deg = 0.f;
    #pragma unroll 10
    for (int j = lane; j < NPIX; j += 32){
        float s = f0*sF[3*j] + f1*sF[3*j+1] + f2*sF[3*j+2];
        s = (s > 0.f) ? s : 0.f;
        rowp[j] = s;
        deg += s;
    }
    #pragma unroll
    for (int o = 16; o; o >>= 1) deg += __shfl_down_sync(0xffffffffu, deg, o);
    // W.max() scaling cancels in D^-1/2 W D^-1/2 ; deg >= 1 (diag is 1)
    if (lane == 0) g_dinv[r] = rsqrtf(deg);
}

// -------- persistent Lanczos (CGS2, 3 grid barriers / iteration) ------------------
// Release: red.release.gpu orders prior stores at GPU scope (no CCTL.IVALL).
// Acquire: ld.acquire.gpu spin with "memory" clobber; cross-block data reads
// all use __ldcg (L2-direct) so stale L1 lines are structurally impossible.
__device__ __forceinline__ void gridbar(unsigned* step){
    __syncthreads();
    if (threadIdx.x == 0){
        unsigned tgt = (++(*step)) * (unsigned)NBLK;
        asm volatile("red.release.gpu.global.add.u32 [%0], %1;"
                     :: "l"(&g_bar), "r"(1u) : "memory");
        unsigned v;
        do {
            asm volatile("ld.acquire.gpu.global.u32 %0, [%1];"
                         : "=r"(v) : "l"(&g_bar) : "memory");
        } while (v < tgt);
    }
    __syncthreads();
}

// coalesced deterministic reduce: sc[i] = sum_b P[b*MLANP + i]  (i<=j), else 0
__device__ __forceinline__ void reduceP(const float* __restrict__ P, float* sc,
                                        float (*s4)[MLANP], int j, int tid){
    int q = tid / MLANP;
    int i = tid - q*MLANP;
    if (q < 4){
        float s = 0.f;
        if (i <= j){
            const float* p = P + (size_t)q*25*MLANP + i;
            #pragma unroll
            for (int bb = 0; bb < 25; bb++) s += __ldcg(p + (size_t)bb*MLANP);
        }
        s4[q][i] = s;
    }
    __syncthreads();
    if (tid < MLANP) sc[tid] = (s4[0][tid] + s4[1][tid]) + (s4[2][tid] + s4[3][tid]);
    __syncthreads();
}

__global__ void __launch_bounds__(NTHR) k_lanczos(){
    __shared__ float Vt[MLANP][TPB+1];  // persistent per-block V slice (own 16 cols)
    __shared__ __align__(16) float sv[NPIX];    // staged v_j
    __shared__ __align__(16) float svd[NPIX];   // dinv .* v_j
    __shared__ __align__(16) float sdinv[NPIX]; // staged dinv (loop-invariant)
    __shared__ float sw2[TPB];          // (I-A)v_j on own cols
    __shared__ float su1[TPB];          // after reorth pass 1, own cols
    __shared__ float sc1[MLANP], sc2[MLANP];
    __shared__ float s4[4][MLANP];      // reduce partials
    __shared__ float sp[32][TPB+1];     // apply-phase stripe partials
    __shared__ float sred[NTHR/32];
    __shared__ float sbinv;
    int tid = threadIdx.x, b = blockIdx.x;
    int lane = tid & 31, w = tid >> 5;  // w = warp id 0..15
    int col0 = b*TPB;
    unsigned bstep = 0;

    // zero V tile (avoid garbage*0 in apply loops for i>j)
    for (int t = tid; t < MLANP*(TPB+1); t += NTHR) ((float*)Vt)[t] = 0.f;
    // stage dinv once (constant during this kernel)
    for (int t = tid; t < NPIX; t += NTHR) sdinv[t] = g_dinv[t];

    // ---- init: own 16 cols of random w + per-block norm partial ----
    if (tid < TPB){
        int p = col0 + tid;
        unsigned u = (unsigned)p*2654435761u + 1234567u;
        u ^= u >> 13; u *= 2246822519u; u ^= u >> 16;
        float v = ((float)(u & 0x7FFFFF))/4194304.0f - 1.0f;
        g_w[p] = v;
        float s = v*v;
        #pragma unroll
        for (int o = 8; o; o >>= 1) s += __shfl_down_sync(0xffffu, s, o);
        if (tid == 0) g_nrm[b] = s;
    }
    gridbar(&bstep);

    for (int j = 0; j < MLAN; j++){
        // ======== Phase A: beta, stage v_j, V append, matvec own rows, dots1 ====
        // prefetch w (float4) concurrently with the nrm reduction
        float x = (tid < NBLK) ? __ldcg(&g_nrm[tid]) : 0.f;
        float4 wv = make_float4(0.f,0.f,0.f,0.f);
        if (tid < NPIX/4) wv = __ldcg(reinterpret_cast<const float4*>(g_w) + tid);
        if (tid < 128){
            #pragma unroll
            for (int o = 16; o; o >>= 1) x += __shfl_down_sync(0xffffffffu, x, o);
            if (lane == 0) sred[w] = x;
        }
        __syncthreads();
        if (tid == 0){
            float s = sred[0] + sred[1] + sred[2] + sred[3];
            float beta = sqrtf(s);
            if (beta < 1e-30f) beta = 1e-30f;
            sbinv = 1.f/beta;
            if (b == 0) g_betaA[j] = beta;
        }
        __syncthreads();
        float binv = sbinv;
        if (tid < NPIX/4){
            float4 v = make_float4(wv.x*binv, wv.y*binv, wv.z*binv, wv.w*binv);
            reinterpret_cast<float4*>(sv)[tid] = v;
            float4 dv = reinterpret_cast<const float4*>(sdinv)[tid];
            reinterpret_cast<float4*>(svd)[tid] =
                make_float4(v.x*dv.x, v.y*dv.y, v.z*dv.z, v.w*dv.w);
        }
        __syncthreads();
        if (tid < TPB) Vt[j][tid] = sv[col0 + tid];
        {   // matvec: warp w computes row r = col0 + w  (own rows == own cols)
            int r = col0 + w;
            const float4* row = (const float4*)(g_A + (size_t)r*NPIX);  // 400 float4
            const float4* svv = (const float4*)svd;
            float acc = 0.f;
            #pragma unroll
            for (int k = 0; k < 12; k++){
                float4 a = row[lane + 32*k];
                float4 c = svv[lane + 32*k];
                acc += a.x*c.x + a.y*c.y + a.z*c.z + a.w*c.w;
            }
            if (lane < 16){
                float4 a = row[384 + lane];
                float4 c = svv[384 + lane];
                acc += a.x*c.x + a.y*c.y + a.z*c.z + a.w*c.w;
            }
            #pragma unroll
            for (int o = 16; o; o >>= 1) acc += __shfl_down_sync(0xffffffffu, acc, o);
            if (lane == 0) sw2[w] = sv[r] - sdinv[r]*acc;   // (I - D^-1/2 W D^-1/2) v_j
        }
        __syncthreads();
        // dots1 partials: P1[b][i] = sum_t Vt[i][t]*sw2[t]  (coalesced write)
        if (tid <= j){
            float a = 0.f;
            #pragma unroll
            for (int t = 0; t < TPB; t++) a += Vt[tid][t]*sw2[t];
            g_P1[(size_t)b*MLANP + tid] = a;
        }
        gridbar(&bstep);

        // ======== Phase C: c1 = reduce(P1); u1 = w2 - V c1; dots2 partials =======
        reduceP(g_P1, sc1, s4, j, tid);
        {
            int tl = tid & (TPB-1), s32 = tid/TPB;     // s32: 0..31
            float a = 0.f;
            #pragma unroll
            for (int q = 0; q < MLANP/32; q++){
                int i = s32*(MLANP/32) + q;
                a += sc1[i]*Vt[i][tl];
            }
            sp[s32][tl] = a;
            __syncthreads();
            if (tid < TPB){
                float v = sw2[tid];
                #pragma unroll
                for (int k = 0; k < 32; k++) v -= sp[k][tid];
                su1[tid] = v;
            }
            __syncthreads();
        }
        if (tid <= j){
            float a = 0.f;
            #pragma unroll
            for (int t = 0; t < TPB; t++) a += Vt[tid][t]*su1[t];
            g_P2[(size_t)b*MLANP + tid] = a;
        }
        gridbar(&bstep);

        // ======== Phase D: c2 = reduce(P2); w_next = u1 - V c2; norm; alpha ======
        reduceP(g_P2, sc2, s4, j, tid);
        {
            int tl = tid & (TPB-1), s32 = tid/TPB;
            float a = 0.f;
            #pragma unroll
            for (int q = 0; q < MLANP/32; q++){
                int i = s32*(MLANP/32) + q;
                a += sc2[i]*Vt[i][tl];
            }
            sp[s32][tl] = a;
            __syncthreads();
            if (tid < TPB){
                float v = su1[tid];
                #pragma unroll
                for (int k = 0; k < 32; k++) v -= sp[k][tid];
                g_w[col0 + tid] = v;
                float s = v*v;
                #pragma unroll
                for (int o = 8; o; o >>= 1) s += __shfl_down_sync(0xffffu, s, o);
                if (tid == 0) g_nrm[b] = s;
            }
            if (b == 0 && tid == 0) g_alphaA[j] = sc1[j] + sc2[j];
        }
        gridbar(&bstep);
    }
}

// -------- tridiagonal bottom-K via Sturm multisection + final loss ------------------
__device__ __forceinline__ int sturm_count(float lam, const float* a, const float* b){
    float d = a[0] - lam;
    if (d == 0.f) d = -1e-25f;
    int c = (d < 0.f);
    for (int i = 1; i < MLAN; i++){
        d = (a[i] - lam) - __fdividef(b[i]*b[i], d);
        if (d == 0.f) d = -1e-25f;
        c += (d < 0.f);
    }
    return c;
}

__global__ void k_trieig(float* __restrict__ out){
    __shared__ float sa[MLAN], sb[MLAN];
    __shared__ int   scnt[1024];
    __shared__ float sblo[KEIG], sbhi[KEIG];
    __shared__ float slo, shi;
    int tid = threadIdx.x;
    if (tid < MLAN){
        sa[tid] = g_alphaA[tid];
        sb[tid] = (tid == 0) ? 0.f : g_betaA[tid];  // sb[i] couples (i-1,i)
    }
    __syncthreads();
    if (tid == 0){
        float lo = 1e30f, hi = -1e30f;
        for (int i = 0; i < MLAN; i++){
            float r = fabsf(sb[i]) + ((i+1 < MLAN) ? fabsf(sb[i+1]) : 0.f);
            lo = fminf(lo, sa[i] - r);
            hi = fmaxf(hi, sa[i] + r);
        }
        slo = lo - 1e-4f; shi = hi + 1e-4f;
    }
    __syncthreads();
    {
        float lam = slo + (shi - slo)*((float)tid/1023.f);
        scnt[tid] = sturm_count(lam, sa, sb);
    }
    __syncthreads();
    if (tid < KEIG){
        int k = tid, tl = 0;
        for (int t = 1; t < 1024; t++) if (scnt[t] <= k) tl = t;
        sblo[k] = slo + (shi - slo)*((float)tl/1023.f);
        sbhi[k] = slo + (shi - slo)*((float)(tl+1)/1023.f);
    }
    __syncthreads();
    for (int round = 0; round < 2; round++){
        int k = tid/100, g = tid%100;
        if (tid < 1000){
            float lam = sblo[k] + (sbhi[k] - sblo[k])*((float)(g+1)/101.f);
            scnt[tid] = sturm_count(lam, sa, sb);
        }
        __syncthreads();
        if (tid < KEIG){
            int k2 = tid, gl = -1;
            for (int g2 = 0; g2 < 100; g2++) if (scnt[k2*100 + g2] <= k2) gl = g2;
            float lo = sblo[k2], w = sbhi[k2] - lo;
            sblo[k2] = lo + w*((float)(gl+1)/101.f);
            sbhi[k2] = lo + w*((float)(gl+2)/101.f);
        }
        __syncthreads();
    }
    // final loss (single thread; lan3[k] = midpoint of bracket k)
    if (tid == 0){
        double s12 = 0.0, s13 = 0.0, s23 = 0.0;
        for (int b = 0; b < NB; b++){
            for (int k = 0; k < KEIG; k++){
                double l1 = (double)g_lan12[b*KEIG + k];
                double l2 = (double)g_lan12[NB*KEIG + b*KEIG + k];
                double l3 = 0.5*((double)sblo[k] + (double)sbhi[k]);
                double d;
                d = l1 - l2; s12 += d*d;
                d = l1 - l3; s13 += d*d;
                d = l2 - l3; s23 += d*d;
            }
        }
        out[0] = (float)(5.0*((s12 + s13 + s23)/(double)(NB*KEIG)));
    }
}

// -------- launch (5 graph nodes total) ----------------------------------------------
extern "C" void kernel_launch(void* const* d_in, const int* in_sizes, int n_in,
                              void* d_out, int out_size){
    const float* feats = (const float*)d_in[0];
    (void)in_sizes; (void)n_in; (void)out_size;   // K = 10, shapes fixed

    k_ds<<<NB*NCH, 256>>>(feats);                 // fused 2-axis downsample
    k_post<<<16 + (NPIX + 255)/256, 256>>>();     // signs + buildF
    k_buildA<<<NBLK, NTHR>>>();                   // W rows + dinv + barrier reset
    k_lanczos<<<NBLK, NTHR>>>();
    k_trieig<<<1, 1024>>>((float*)d_out);         // eig + loss fused
}